// round 9
// baseline (speedup 1.0000x reference)
#include <cuda_runtime.h>
#include <math.h>
#include <stdint.h>

// ---------------------------------------------------------------------------
// Problem constants
// ---------------------------------------------------------------------------
#define BATCH      512
#define SEQ        64
#define DIM        1024
#define NUM_ACT    8
#define ABINS      256
#define D_STATE    16
#define D_CONV     4
#define D_INNER    2048
#define DT_RANK    64
#define XD         96
#define ROWS       (BATCH * NUM_ACT)        // 4096
#define TABROWS    ((NUM_ACT - 1) * ABINS)  // 1792

// ---------------------------------------------------------------------------
// Scratch (static device allocations; no cudaMalloc allowed)
// ---------------------------------------------------------------------------
__device__ float d_sos    [BATCH * DIM];
__device__ float d_tproj  [TABROWS * 2 * D_INNER];
__device__ float d_sosproj[BATCH * 2 * D_INNER];
__device__ float d_xc     [ROWS * D_INNER];
__device__ float d_xdbl   [ROWS * XD];
__device__ float d_delta  [ROWS * D_INNER];
__device__ float d_y      [ROWS * D_INNER];
__device__ float d_embed  [ROWS * DIM];

// ---------------------------------------------------------------------------
// TF32 tensor-core NT GEMM with cp.async staging + ldmatrix fragments.
//   C[m,n] = sum_k A[m,k]*B[n,k]
//   Block tile 128x128x16, 8 warps, warp tile 64x32 (m16n8k8 MMAs).
//   Requirements: M % 128 == 0, K % 16 == 0, lda/ldb % 4 == 0,
//                 A/B base pointers 16B-aligned. N guarded (zero-filled).
//   EPI: 0 none | 1 softplus(x+bias[n]) | 2 sigmoid, stored at (n+255)&255
// ---------------------------------------------------------------------------
#define BM  128
#define BN  128
#define BK  16
#define BKP 20   // pitch (floats): bank(row) = 20*row mod 32 -> {0,4,..,28}

__device__ __forceinline__ void cp_async16(uint32_t dst, const void* src,
                                           int src_bytes) {
    asm volatile("cp.async.cg.shared.global [%0], [%1], 16, %2;\n"
                 :: "r"(dst), "l"(src), "r"(src_bytes));
}

__device__ __forceinline__ void ldsm_x4(unsigned r[4], uint32_t addr) {
    asm volatile("ldmatrix.sync.aligned.m8n8.x4.shared.b16 {%0,%1,%2,%3}, [%4];\n"
                 : "=r"(r[0]), "=r"(r[1]), "=r"(r[2]), "=r"(r[3])
                 : "r"(addr));
}

__device__ __forceinline__ void mma_tf32(float c[4],
                                         const unsigned a[4],
                                         const unsigned b[2]) {
    asm volatile(
        "mma.sync.aligned.m16n8k8.row.col.f32.tf32.tf32.f32 "
        "{%0,%1,%2,%3}, {%4,%5,%6,%7}, {%8,%9}, {%0,%1,%2,%3};\n"
        : "+f"(c[0]), "+f"(c[1]), "+f"(c[2]), "+f"(c[3])
        : "r"(a[0]), "r"(a[1]), "r"(a[2]), "r"(a[3]),
          "r"(b[0]), "r"(b[1]));
}

template<int EPI>
__global__ __launch_bounds__(256)
void gemm_tf32(const float* __restrict__ Ag, const float* __restrict__ Bg,
               float* __restrict__ Cg, int M, int N, int K,
               int lda, int ldb, int ldc,
               long sAz, long sBz, long sCz,
               const float* __restrict__ bias)
{
    const float* A = Ag + (long)blockIdx.z * sAz;
    const float* B = Bg + (long)blockIdx.z * sBz;
    float*       C = Cg + (long)blockIdx.z * sCz;

    __shared__ float As[2][BM][BKP];   // 20 KB
    __shared__ float Bs[2][BN][BKP];   // 20 KB

    const int tid  = threadIdx.x;
    const int warp = tid >> 5;
    const int lane = tid & 31;
    const int wm   = (warp >> 2) * 64;
    const int wn   = (warp & 3)  * 32;
    const int gid  = lane >> 2;
    const int tig  = lane & 3;

    const int bm = blockIdx.y * BM;
    const int bn = blockIdx.x * BN;

    const int lr = tid >> 2;              // 0..63 (stage row)
    const int lc = (tid & 3) * 4;         // 0,4,8,12 (stage k, 16B)

    const uint32_t sA = (uint32_t)__cvta_generic_to_shared(&As[0][0][0]);
    const uint32_t sB = (uint32_t)__cvta_generic_to_shared(&Bs[0][0][0]);
    const uint32_t bufB = BM * BKP * 4;   // bytes per buffer

    // ldmatrix per-lane offsets (bytes), layouts verified against mma frags:
    // A x4 tiles: (r0..7,k0..3)(r8..15,k0..3)(r0..7,k4..7)(r8..15,k4..7)
    const int a_row = (lane & 7) + ((lane >> 3) & 1) * 8;
    const int a_col = (lane >> 4) * 4;
    const uint32_t a_off = (uint32_t)(a_row * BKP + a_col) * 4;
    // B x4 tiles: (n0..7,k0..3)(n0..7,k4..7)(n8..15,k0..3)(n8..15,k4..7)
    const int b_row = (lane & 7) + ((lane >> 4) ? 8 : 0);
    const int b_col = ((lane >> 3) & 1) * 4;
    const uint32_t b_off = (uint32_t)(b_row * BKP + b_col) * 4;

    float acc[4][4][4];
    #pragma unroll
    for (int i = 0; i < 4; i++)
        #pragma unroll
        for (int j = 0; j < 4; j++)
            #pragma unroll
            for (int e = 0; e < 4; e++) acc[i][j][e] = 0.f;

    auto issue = [&](int it) {
        const int k0  = it * BK;
        const int buf = it & 1;
        #pragma unroll
        for (int r = 0; r < 2; r++) {
            int row = lr + r * 64;
            cp_async16(sA + buf * bufB + (uint32_t)(row * BKP + lc) * 4,
                       A + (long)(bm + row) * lda + k0 + lc, 16);
            int brow = bn + row;
            const float* bp = (brow < N) ? (B + (long)brow * ldb + k0 + lc) : B;
            cp_async16(sB + buf * bufB + (uint32_t)(row * BKP + lc) * 4,
                       bp, (brow < N) ? 16 : 0);
        }
    };

    const int nk = K / BK;
    issue(0);
    asm volatile("cp.async.commit_group;\n");

    for (int it = 0; it < nk; ++it) {
        asm volatile("cp.async.wait_group 0;\n");
        __syncthreads();
        if (it + 1 < nk) {
            issue(it + 1);
            asm volatile("cp.async.commit_group;\n");
        }
        const int buf = it & 1;
        const uint32_t aBase = sA + buf * bufB + a_off;
        const uint32_t bBase = sB + buf * bufB + b_off;

        #pragma unroll
        for (int kk = 0; kk < BK; kk += 8) {
            unsigned a[4][4], b[2][4];
            #pragma unroll
            for (int mt = 0; mt < 4; mt++)
                ldsm_x4(a[mt], aBase + (uint32_t)((wm + mt * 16) * BKP + kk) * 4);
            #pragma unroll
            for (int np = 0; np < 2; np++)
                ldsm_x4(b[np], bBase + (uint32_t)((wn + np * 16) * BKP + kk) * 4);
            #pragma unroll
            for (int mt = 0; mt < 4; mt++)
                #pragma unroll
                for (int nt = 0; nt < 4; nt++)
                    mma_tf32(acc[mt][nt], a[mt], &b[nt >> 1][(nt & 1) * 2]);
        }
        __syncthreads();   // all warps done reading buf before it is refilled
    }

    // --- epilogue ---
    #pragma unroll
    for (int mt = 0; mt < 4; mt++) {
        int m0 = bm + wm + mt * 16 + gid;
        #pragma unroll
        for (int nt = 0; nt < 4; nt++) {
            int col0 = bn + wn + nt * 8 + tig * 2;
            #pragma unroll
            for (int e = 0; e < 4; e++) {
                int m = m0 + ((e >> 1) ? 8 : 0);
                int n = col0 + (e & 1);
                if (n < N) {
                    float v = acc[mt][nt][e];
                    if (EPI == 1) {                 // bias + softplus (stable)
                        v += bias[n];
                        v = fmaxf(v, 0.f) + log1pf(expf(-fabsf(v)));
                    }
                    int nout = n;
                    if (EPI == 2) {                 // sigmoid + roll(-1)
                        nout = (n + 255) & 255;
                        v = 1.f / (1.f + __expf(-v));
                    }
                    C[(long)m * ldc + nout] = v;
                }
            }
        }
    }
}

// ---------------------------------------------------------------------------
// sos = mean over seq axis of encoded_state  [b, 64, 1024] -> [b, 1024]
// ---------------------------------------------------------------------------
__global__ void mean_kernel(const float* __restrict__ es, float* __restrict__ sos)
{
    int b = blockIdx.x;
    for (int d = threadIdx.x; d < DIM; d += blockDim.x) {
        const float* p = es + (long)b * SEQ * DIM + d;
        float s = 0.f;
        #pragma unroll
        for (int t = 0; t < SEQ; t++) s += p[(long)t * DIM];
        sos[b * DIM + d] = s * (1.f / SEQ);
    }
}

__device__ __forceinline__ const float* xz_row(int b, int t,
                                               const int* __restrict__ actions,
                                               const float* __restrict__ sosproj,
                                               const float* __restrict__ tproj)
{
    if (t == 0) return sosproj + (long)b * (2 * D_INNER);
    int act = actions[b * (NUM_ACT - 1) + (t - 1)];
    return tproj + (long)((t - 1) * ABINS + act) * (2 * D_INNER);
}

// ---------------------------------------------------------------------------
// Causal depthwise conv (D_CONV=4) + SiLU. One block per token row (b,l).
// ---------------------------------------------------------------------------
__global__ void conv_silu_kernel(const int* __restrict__ actions,
                                 const float* __restrict__ sosproj,
                                 const float* __restrict__ tproj,
                                 const float* __restrict__ conv_w,
                                 const float* __restrict__ conv_b,
                                 float* __restrict__ xc)
{
    int row = blockIdx.x;
    int b = row >> 3, l = row & 7;
    const float* p[4];
    #pragma unroll
    for (int k = 0; k < 4; k++) {
        int t = l + k - 3;
        p[k] = (t >= 0) ? xz_row(b, t, actions, sosproj, tproj) : nullptr;
    }
    for (int c = threadIdx.x; c < D_INNER; c += blockDim.x) {
        float a = conv_b[c];
        #pragma unroll
        for (int k = 0; k < 4; k++)
            if (p[k]) a = fmaf(p[k][c], conv_w[c * 4 + k], a);
        xc[(long)row * D_INNER + c] = a / (1.f + __expf(-a));
    }
}

// ---------------------------------------------------------------------------
// Selective scan + skip (u*D) + SiLU(z) gating. One block per batch b.
// ---------------------------------------------------------------------------
__global__ void scan_kernel(const float* __restrict__ xc,
                            const float* __restrict__ delta,
                            const float* __restrict__ xdbl,
                            const int*   __restrict__ actions,
                            const float* __restrict__ sosproj,
                            const float* __restrict__ tproj,
                            const float* __restrict__ A_log,
                            const float* __restrict__ Dp,
                            float* __restrict__ y)
{
    int b = blockIdx.x;
    int tid = threadIdx.x;

    __shared__ float Bs[NUM_ACT][D_STATE];
    __shared__ float Cs[NUM_ACT][D_STATE];
    if (tid < NUM_ACT * D_STATE) {
        int l = tid / D_STATE, n = tid % D_STATE;
        const float* r = xdbl + (long)(b * NUM_ACT + l) * XD;
        Bs[l][n] = r[DT_RANK + n];
        Cs[l][n] = r[DT_RANK + D_STATE + n];
    }
    __syncthreads();

    const float* zp[NUM_ACT];
    #pragma unroll
    for (int l = 0; l < NUM_ACT; l++)
        zp[l] = xz_row(b, l, actions, sosproj, tproj) + D_INNER;

    for (int j = 0; j < D_INNER / 256; j++) {
        int d = tid + j * 256;
        float Arow[D_STATE];
        #pragma unroll
        for (int n = 0; n < D_STATE; n++)
            Arow[n] = -__expf(A_log[d * D_STATE + n]);
        float Dd = Dp[d];
        float h[D_STATE];
        #pragma unroll
        for (int n = 0; n < D_STATE; n++) h[n] = 0.f;

        #pragma unroll
        for (int l = 0; l < NUM_ACT; l++) {
            long row = (long)(b * NUM_ACT + l);
            float dl = delta[row * D_INNER + d];
            float u  = xc[row * D_INNER + d];
            float du = dl * u;
            float yv = 0.f;
            #pragma unroll
            for (int n = 0; n < D_STATE; n++) {
                float dA = __expf(dl * Arow[n]);
                h[n] = fmaf(dA, h[n], du * Bs[l][n]);
                yv   = fmaf(h[n], Cs[l][n], yv);
            }
            yv = fmaf(u, Dd, yv);
            float z = zp[l][d];
            float sz = z / (1.f + __expf(-z));
            y[row * D_INNER + d] = yv * sz;
        }
    }
}

// ---------------------------------------------------------------------------
// Launch
// ---------------------------------------------------------------------------
extern "C" void kernel_launch(void* const* d_in, const int* in_sizes, int n_in,
                              void* d_out, int out_size)
{
    const float* encoded_state = (const float*)d_in[0];
    const int*   actions       = (const int*)  d_in[1];
    const float* tab           = (const float*)d_in[2];   // [8,256,1024]
    /* d_in[3] = gamma (unused by reference) */
    const float* in_proj_w     = (const float*)d_in[4];   // [4096,1024]
    const float* conv_w        = (const float*)d_in[5];
    const float* conv_b        = (const float*)d_in[6];
    const float* x_proj_w      = (const float*)d_in[7];   // [96,2048]
    const float* dt_proj_w     = (const float*)d_in[8];   // [2048,64]
    const float* dt_proj_b     = (const float*)d_in[9];
    const float* A_log         = (const float*)d_in[10];
    const float* D_param       = (const float*)d_in[11];
    const float* out_proj_w    = (const float*)d_in[12];  // [1024,2048]
    float* out = (float*)d_out;                           // [512,8,256]

    float *g_sos, *g_tproj, *g_sosproj, *g_xc, *g_xdbl, *g_delta, *g_y, *g_embed;
    cudaGetSymbolAddress((void**)&g_sos,     d_sos);
    cudaGetSymbolAddress((void**)&g_tproj,   d_tproj);
    cudaGetSymbolAddress((void**)&g_sosproj, d_sosproj);
    cudaGetSymbolAddress((void**)&g_xc,      d_xc);
    cudaGetSymbolAddress((void**)&g_xdbl,    d_xdbl);
    cudaGetSymbolAddress((void**)&g_delta,   d_delta);
    cudaGetSymbolAddress((void**)&g_y,       d_y);
    cudaGetSymbolAddress((void**)&g_embed,   d_embed);

    // 1) sos = mean(encoded_state, axis=seq)
    mean_kernel<<<BATCH, 256>>>(encoded_state, g_sos);

    // 2) tproj = bin_table[0:7*256] @ in_proj_w^T   (1792 x 4096, K=1024)
    gemm_tf32<0><<<dim3(2 * D_INNER / BN, TABROWS / BM, 1), 256>>>(
        tab, in_proj_w, g_tproj, TABROWS, 2 * D_INNER, DIM,
        DIM, DIM, 2 * D_INNER, 0, 0, 0, nullptr);

    // 3) sosproj = sos @ in_proj_w^T   (512 x 4096, K=1024)
    gemm_tf32<0><<<dim3(2 * D_INNER / BN, BATCH / BM, 1), 256>>>(
        g_sos, in_proj_w, g_sosproj, BATCH, 2 * D_INNER, DIM,
        DIM, DIM, 2 * D_INNER, 0, 0, 0, nullptr);

    // 4) xc = silu(causal_conv(xh)), xh gathered from {sosproj, tproj}
    conv_silu_kernel<<<ROWS, 256>>>(actions, g_sosproj, g_tproj,
                                    conv_w, conv_b, g_xc);

    // 5) x_dbl = xc @ x_proj_w^T   (4096 x 96, K=2048)
    gemm_tf32<0><<<dim3(1, ROWS / BM, 1), 256>>>(
        g_xc, x_proj_w, g_xdbl, ROWS, XD, D_INNER,
        D_INNER, D_INNER, XD, 0, 0, 0, nullptr);

    // 6) delta = softplus(dt @ dt_proj_w^T + dt_proj_b)  (4096 x 2048, K=64)
    gemm_tf32<1><<<dim3(D_INNER / BN, ROWS / BM, 1), 256>>>(
        g_xdbl, dt_proj_w, g_delta, ROWS, D_INNER, DT_RANK,
        XD, DT_RANK, D_INNER, 0, 0, 0, dt_proj_b);

    // 7) selective scan + u*D + silu(z) gating
    scan_kernel<<<BATCH, 256>>>(g_xc, g_delta, g_xdbl, actions,
                                g_sosproj, g_tproj, A_log, D_param, g_y);

    // 8) embed = y @ out_proj_w^T   (4096 x 1024, K=2048)
    gemm_tf32<0><<<dim3(DIM / BN, ROWS / BM, 1), 256>>>(
        g_y, out_proj_w, g_embed, ROWS, DIM, D_INNER,
        D_INNER, D_INNER, DIM, 0, 0, 0, nullptr);

    // 9) out[b,n,a] = sigmoid( embed[b,n,:] . tab[n,(a+1)%256,:] )
    gemm_tf32<2><<<dim3(ABINS / BN, BATCH / BM, NUM_ACT), 256>>>(
        g_embed, tab, out, BATCH, ABINS, DIM,
        NUM_ACT * DIM, DIM, NUM_ACT * ABINS,
        DIM, (long)ABINS * DIM, ABINS,
        nullptr);
}

// round 14
// speedup vs baseline: 1.6143x; 1.6143x over previous
#include <cuda_runtime.h>
#include <cuda_bf16.h>
#include <math.h>
#include <stdint.h>

// ---------------------------------------------------------------------------
// Problem constants
// ---------------------------------------------------------------------------
#define BATCH      512
#define SEQ        64
#define DIM        1024
#define NUM_ACT    8
#define ABINS      256
#define D_STATE    16
#define D_CONV     4
#define D_INNER    2048
#define DT_RANK    64
#define XD         96
#define ROWS       (BATCH * NUM_ACT)        // 4096
#define TABROWS    ((NUM_ACT - 1) * ABINS)  // 1792

// ---------------------------------------------------------------------------
// Scratch (static device allocations; no cudaMalloc allowed)
// ---------------------------------------------------------------------------
__device__ float d_sos    [BATCH * DIM];
__device__ float d_tproj  [TABROWS * 2 * D_INNER];
__device__ float d_sosproj[BATCH * 2 * D_INNER];
__device__ float d_xc     [ROWS * D_INNER];
__device__ float d_xdbl   [ROWS * XD];
__device__ float d_delta  [ROWS * D_INNER];
__device__ float d_y      [ROWS * D_INNER];
__device__ float d_embed  [ROWS * DIM];

// ---------------------------------------------------------------------------
// BF16 tensor-core NT GEMM: C[m,n] = sum_k A[m,k]*B[n,k]  (A,B fp32 in gmem,
// converted to bf16 during smem staging; fp32 accumulate).
//   Block tile 128x128x32, 8 warps, warp tile 64x32 (m16n8k16 MMAs).
//   Requirements: M % 128 == 0, K % 32 == 0, lda/ldb % 4 == 0,
//                 A/B 16B-aligned. N guarded (zero-filled rows / masked cols).
//   EPI: 0 none | 1 softplus(x+bias[n]) | 2 sigmoid, stored at (n+255)&255
// ---------------------------------------------------------------------------
#define BM  128
#define BN  128
#define BK  32   // bf16 elements along K per stage
#define BKP 40   // smem pitch (bf16 elems): row base = 80B*r -> 8 distinct 16B banks

__device__ __forceinline__ void ldsm_x4(unsigned r[4], uint32_t addr) {
    asm volatile("ldmatrix.sync.aligned.m8n8.x4.shared.b16 {%0,%1,%2,%3}, [%4];\n"
                 : "=r"(r[0]), "=r"(r[1]), "=r"(r[2]), "=r"(r[3])
                 : "r"(addr));
}

__device__ __forceinline__ void mma_bf16(float c[4],
                                         const unsigned a[4],
                                         const unsigned b[2]) {
    asm volatile(
        "mma.sync.aligned.m16n8k16.row.col.f32.bf16.bf16.f32 "
        "{%0,%1,%2,%3}, {%4,%5,%6,%7}, {%8,%9}, {%0,%1,%2,%3};\n"
        : "+f"(c[0]), "+f"(c[1]), "+f"(c[2]), "+f"(c[3])
        : "r"(a[0]), "r"(a[1]), "r"(a[2]), "r"(a[3]),
          "r"(b[0]), "r"(b[1]));
}

__device__ __forceinline__ uint4 cvt8_bf16(const float4& a, const float4& b) {
    __nv_bfloat162 p0 = __float22bfloat162_rn(make_float2(a.x, a.y));
    __nv_bfloat162 p1 = __float22bfloat162_rn(make_float2(a.z, a.w));
    __nv_bfloat162 p2 = __float22bfloat162_rn(make_float2(b.x, b.y));
    __nv_bfloat162 p3 = __float22bfloat162_rn(make_float2(b.z, b.w));
    uint4 u;
    u.x = *reinterpret_cast<unsigned*>(&p0);
    u.y = *reinterpret_cast<unsigned*>(&p1);
    u.z = *reinterpret_cast<unsigned*>(&p2);
    u.w = *reinterpret_cast<unsigned*>(&p3);
    return u;
}

template<int EPI>
__global__ __launch_bounds__(256)
void gemm_bf16(const float* __restrict__ Ag, const float* __restrict__ Bg,
               float* __restrict__ Cg, int M, int N, int K,
               int lda, int ldb, int ldc,
               long sAz, long sBz, long sCz,
               const float* __restrict__ bias)
{
    const float* A = Ag + (long)blockIdx.z * sAz;
    const float* B = Bg + (long)blockIdx.z * sBz;
    float*       C = Cg + (long)blockIdx.z * sCz;

    __shared__ alignas(16) __nv_bfloat16 As[2][BM][BKP];   // 20 KB
    __shared__ alignas(16) __nv_bfloat16 Bs[2][BN][BKP];   // 20 KB

    const int tid  = threadIdx.x;
    const int warp = tid >> 5;
    const int lane = tid & 31;
    const int wm   = (warp >> 2) * 64;    // 0 or 64
    const int wn   = (warp & 3)  * 32;    // 0,32,64,96
    const int gid  = lane >> 2;
    const int tig  = lane & 3;

    const int bm = blockIdx.y * BM;
    const int bn = blockIdx.x * BN;

    const int lr = tid >> 2;              // 0..63 (stage row)
    const int lc = (tid & 3) * 8;         // 0,8,16,24 (stage k, 8 floats)

    const uint32_t sA = (uint32_t)__cvta_generic_to_shared(&As[0][0][0]);
    const uint32_t sB = (uint32_t)__cvta_generic_to_shared(&Bs[0][0][0]);
    const uint32_t bufBytes = BM * BKP * 2;   // per buffer

    // ldmatrix per-lane offsets (bytes). Mappings verified in R9, rescaled to
    // bf16 (16B unit = 8 elements):
    //  A x4: (r0-7,k0-7)(r8-15,k0-7)(r0-7,k8-15)(r8-15,k8-15)
    const int a_row = (lane & 7) + ((lane >> 3) & 1) * 8;
    const uint32_t a_off = (uint32_t)(a_row * BKP + (lane >> 4) * 8) * 2;
    //  B x4: (n0-7,k0-7)(n0-7,k8-15)(n8-15,k0-7)(n8-15,k8-15)
    const int b_row = (lane & 7) + ((lane >> 4) ? 8 : 0);
    const uint32_t b_off = (uint32_t)(b_row * BKP + ((lane >> 3) & 1) * 8) * 2;

    float acc[4][4][4];
    #pragma unroll
    for (int i = 0; i < 4; i++)
        #pragma unroll
        for (int j = 0; j < 4; j++)
            #pragma unroll
            for (int e = 0; e < 4; e++) acc[i][j][e] = 0.f;

    float4 av[2][2], bv[2][2];
    const float4 z4 = make_float4(0.f, 0.f, 0.f, 0.f);

    auto load_g = [&](int k0) {
        #pragma unroll
        for (int r = 0; r < 2; r++) {
            int row = lr + r * 64;
            #pragma unroll
            for (int q = 0; q < 2; q++)
                av[r][q] = *reinterpret_cast<const float4*>(
                    A + (long)(bm + row) * lda + k0 + lc + q * 4);
            int brow = bn + row;
            #pragma unroll
            for (int q = 0; q < 2; q++)
                bv[r][q] = (brow < N)
                    ? *reinterpret_cast<const float4*>(
                          B + (long)brow * ldb + k0 + lc + q * 4)
                    : z4;
        }
    };

    auto store_s = [&](int buf) {
        #pragma unroll
        for (int r = 0; r < 2; r++) {
            int row = lr + r * 64;
            *reinterpret_cast<uint4*>(&As[buf][row][lc]) =
                cvt8_bf16(av[r][0], av[r][1]);
            *reinterpret_cast<uint4*>(&Bs[buf][row][lc]) =
                cvt8_bf16(bv[r][0], bv[r][1]);
        }
    };

    const int nk = K / BK;
    load_g(0);
    store_s(0);
    __syncthreads();

    for (int it = 0; it < nk; ++it) {
        if (it + 1 < nk) load_g((it + 1) * BK);
        const int buf = it & 1;
        const uint32_t aBase = sA + buf * bufBytes + a_off;
        const uint32_t bBase = sB + buf * bufBytes + b_off;

        #pragma unroll
        for (int kk = 0; kk < BK; kk += 16) {
            unsigned a[4][4], b[2][4];
            #pragma unroll
            for (int mt = 0; mt < 4; mt++)
                ldsm_x4(a[mt], aBase + (uint32_t)((wm + mt * 16) * BKP + kk) * 2);
            #pragma unroll
            for (int np = 0; np < 2; np++)
                ldsm_x4(b[np], bBase + (uint32_t)((wn + np * 16) * BKP + kk) * 2);
            #pragma unroll
            for (int mt = 0; mt < 4; mt++)
                #pragma unroll
                for (int nt = 0; nt < 4; nt++)
                    mma_bf16(acc[mt][nt], a[mt], &b[nt >> 1][(nt & 1) * 2]);
        }

        if (it + 1 < nk) store_s((it + 1) & 1);
        __syncthreads();
    }

    // --- epilogue ---
    #pragma unroll
    for (int mt = 0; mt < 4; mt++) {
        int m0 = bm + wm + mt * 16 + gid;
        #pragma unroll
        for (int nt = 0; nt < 4; nt++) {
            int col0 = bn + wn + nt * 8 + tig * 2;
            #pragma unroll
            for (int e = 0; e < 4; e++) {
                int m = m0 + ((e >> 1) ? 8 : 0);
                int n = col0 + (e & 1);
                if (n < N) {
                    float v = acc[mt][nt][e];
                    if (EPI == 1) {                 // bias + softplus (stable)
                        v += bias[n];
                        v = fmaxf(v, 0.f) + log1pf(expf(-fabsf(v)));
                    }
                    int nout = n;
                    if (EPI == 2) {                 // sigmoid + roll(-1)
                        nout = (n + 255) & 255;
                        v = 1.f / (1.f + __expf(-v));
                    }
                    C[(long)m * ldc + nout] = v;
                }
            }
        }
    }
}

// ---------------------------------------------------------------------------
// sos = mean over seq axis of encoded_state  [b, 64, 1024] -> [b, 1024]
// ---------------------------------------------------------------------------
__global__ void mean_kernel(const float* __restrict__ es, float* __restrict__ sos)
{
    int b = blockIdx.x;
    for (int d = threadIdx.x; d < DIM; d += blockDim.x) {
        const float* p = es + (long)b * SEQ * DIM + d;
        float s = 0.f;
        #pragma unroll
        for (int t = 0; t < SEQ; t++) s += p[(long)t * DIM];
        sos[b * DIM + d] = s * (1.f / SEQ);
    }
}

__device__ __forceinline__ const float* xz_row(int b, int t,
                                               const int* __restrict__ actions,
                                               const float* __restrict__ sosproj,
                                               const float* __restrict__ tproj)
{
    if (t == 0) return sosproj + (long)b * (2 * D_INNER);
    int act = actions[b * (NUM_ACT - 1) + (t - 1)];
    return tproj + (long)((t - 1) * ABINS + act) * (2 * D_INNER);
}

// ---------------------------------------------------------------------------
// Causal depthwise conv (D_CONV=4) + SiLU. One block per token row (b,l).
// ---------------------------------------------------------------------------
__global__ void conv_silu_kernel(const int* __restrict__ actions,
                                 const float* __restrict__ sosproj,
                                 const float* __restrict__ tproj,
                                 const float* __restrict__ conv_w,
                                 const float* __restrict__ conv_b,
                                 float* __restrict__ xc)
{
    int row = blockIdx.x;
    int b = row >> 3, l = row & 7;
    const float* p[4];
    #pragma unroll
    for (int k = 0; k < 4; k++) {
        int t = l + k - 3;
        p[k] = (t >= 0) ? xz_row(b, t, actions, sosproj, tproj) : nullptr;
    }
    for (int c = threadIdx.x; c < D_INNER; c += blockDim.x) {
        float a = conv_b[c];
        #pragma unroll
        for (int k = 0; k < 4; k++)
            if (p[k]) a = fmaf(p[k][c], conv_w[c * 4 + k], a);
        xc[(long)row * D_INNER + c] = a / (1.f + __expf(-a));
    }
}

// ---------------------------------------------------------------------------
// Selective scan + skip (u*D) + SiLU(z) gating. One block per batch b.
// ---------------------------------------------------------------------------
__global__ void scan_kernel(const float* __restrict__ xc,
                            const float* __restrict__ delta,
                            const float* __restrict__ xdbl,
                            const int*   __restrict__ actions,
                            const float* __restrict__ sosproj,
                            const float* __restrict__ tproj,
                            const float* __restrict__ A_log,
                            const float* __restrict__ Dp,
                            float* __restrict__ y)
{
    int b = blockIdx.x;
    int tid = threadIdx.x;

    __shared__ float Bs[NUM_ACT][D_STATE];
    __shared__ float Cs[NUM_ACT][D_STATE];
    if (tid < NUM_ACT * D_STATE) {
        int l = tid / D_STATE, n = tid % D_STATE;
        const float* r = xdbl + (long)(b * NUM_ACT + l) * XD;
        Bs[l][n] = r[DT_RANK + n];
        Cs[l][n] = r[DT_RANK + D_STATE + n];
    }
    __syncthreads();

    const float* zp[NUM_ACT];
    #pragma unroll
    for (int l = 0; l < NUM_ACT; l++)
        zp[l] = xz_row(b, l, actions, sosproj, tproj) + D_INNER;

    for (int j = 0; j < D_INNER / 256; j++) {
        int d = tid + j * 256;
        float Arow[D_STATE];
        #pragma unroll
        for (int n = 0; n < D_STATE; n++)
            Arow[n] = -__expf(A_log[d * D_STATE + n]);
        float Dd = Dp[d];
        float h[D_STATE];
        #pragma unroll
        for (int n = 0; n < D_STATE; n++) h[n] = 0.f;

        #pragma unroll
        for (int l = 0; l < NUM_ACT; l++) {
            long row = (long)(b * NUM_ACT + l);
            float dl = delta[row * D_INNER + d];
            float u  = xc[row * D_INNER + d];
            float du = dl * u;
            float yv = 0.f;
            #pragma unroll
            for (int n = 0; n < D_STATE; n++) {
                float dA = __expf(dl * Arow[n]);
                h[n] = fmaf(dA, h[n], du * Bs[l][n]);
                yv   = fmaf(h[n], Cs[l][n], yv);
            }
            yv = fmaf(u, Dd, yv);
            float z = zp[l][d];
            float sz = z / (1.f + __expf(-z));
            y[row * D_INNER + d] = yv * sz;
        }
    }
}

// ---------------------------------------------------------------------------
// Launch
// ---------------------------------------------------------------------------
extern "C" void kernel_launch(void* const* d_in, const int* in_sizes, int n_in,
                              void* d_out, int out_size)
{
    const float* encoded_state = (const float*)d_in[0];
    const int*   actions       = (const int*)  d_in[1];
    const float* tab           = (const float*)d_in[2];   // [8,256,1024]
    /* d_in[3] = gamma (unused by reference) */
    const float* in_proj_w     = (const float*)d_in[4];   // [4096,1024]
    const float* conv_w        = (const float*)d_in[5];
    const float* conv_b        = (const float*)d_in[6];
    const float* x_proj_w      = (const float*)d_in[7];   // [96,2048]
    const float* dt_proj_w     = (const float*)d_in[8];   // [2048,64]
    const float* dt_proj_b     = (const float*)d_in[9];
    const float* A_log         = (const float*)d_in[10];
    const float* D_param       = (const float*)d_in[11];
    const float* out_proj_w    = (const float*)d_in[12];  // [1024,2048]
    float* out = (float*)d_out;                           // [512,8,256]

    float *g_sos, *g_tproj, *g_sosproj, *g_xc, *g_xdbl, *g_delta, *g_y, *g_embed;
    cudaGetSymbolAddress((void**)&g_sos,     d_sos);
    cudaGetSymbolAddress((void**)&g_tproj,   d_tproj);
    cudaGetSymbolAddress((void**)&g_sosproj, d_sosproj);
    cudaGetSymbolAddress((void**)&g_xc,      d_xc);
    cudaGetSymbolAddress((void**)&g_xdbl,    d_xdbl);
    cudaGetSymbolAddress((void**)&g_delta,   d_delta);
    cudaGetSymbolAddress((void**)&g_y,       d_y);
    cudaGetSymbolAddress((void**)&g_embed,   d_embed);

    // 1) sos = mean(encoded_state, axis=seq)
    mean_kernel<<<BATCH, 256>>>(encoded_state, g_sos);

    // 2) tproj = bin_table[0:7*256] @ in_proj_w^T   (1792 x 4096, K=1024)
    gemm_bf16<0><<<dim3(2 * D_INNER / BN, TABROWS / BM, 1), 256>>>(
        tab, in_proj_w, g_tproj, TABROWS, 2 * D_INNER, DIM,
        DIM, DIM, 2 * D_INNER, 0, 0, 0, nullptr);

    // 3) sosproj = sos @ in_proj_w^T   (512 x 4096, K=1024)
    gemm_bf16<0><<<dim3(2 * D_INNER / BN, BATCH / BM, 1), 256>>>(
        g_sos, in_proj_w, g_sosproj, BATCH, 2 * D_INNER, DIM,
        DIM, DIM, 2 * D_INNER, 0, 0, 0, nullptr);

    // 4) xc = silu(causal_conv(xh)), xh gathered from {sosproj, tproj}
    conv_silu_kernel<<<ROWS, 256>>>(actions, g_sosproj, g_tproj,
                                    conv_w, conv_b, g_xc);

    // 5) x_dbl = xc @ x_proj_w^T   (4096 x 96, K=2048)
    gemm_bf16<0><<<dim3(1, ROWS / BM, 1), 256>>>(
        g_xc, x_proj_w, g_xdbl, ROWS, XD, D_INNER,
        D_INNER, D_INNER, XD, 0, 0, 0, nullptr);

    // 6) delta = softplus(dt @ dt_proj_w^T + dt_proj_b)  (4096 x 2048, K=64)
    gemm_bf16<1><<<dim3(D_INNER / BN, ROWS / BM, 1), 256>>>(
        g_xdbl, dt_proj_w, g_delta, ROWS, D_INNER, DT_RANK,
        XD, DT_RANK, D_INNER, 0, 0, 0, dt_proj_b);

    // 7) selective scan + u*D + silu(z) gating
    scan_kernel<<<BATCH, 256>>>(g_xc, g_delta, g_xdbl, actions,
                                g_sosproj, g_tproj, A_log, D_param, g_y);

    // 8) embed = y @ out_proj_w^T   (4096 x 1024, K=2048)
    gemm_bf16<0><<<dim3(DIM / BN, ROWS / BM, 1), 256>>>(
        g_y, out_proj_w, g_embed, ROWS, DIM, D_INNER,
        D_INNER, D_INNER, DIM, 0, 0, 0, nullptr);

    // 9) out[b,n,a] = sigmoid( embed[b,n,:] . tab[n,(a+1)%256,:] )
    gemm_bf16<2><<<dim3(ABINS / BN, BATCH / BM, NUM_ACT), 256>>>(
        g_embed, tab, out, BATCH, ABINS, DIM,
        NUM_ACT * DIM, DIM, NUM_ACT * ABINS,
        DIM, (long)ABINS * DIM, ABINS,
        nullptr);
}

// round 15
// speedup vs baseline: 1.8500x; 1.1461x over previous
#include <cuda_runtime.h>
#include <cuda_bf16.h>
#include <math.h>
#include <stdint.h>

// ---------------------------------------------------------------------------
// Problem constants
// ---------------------------------------------------------------------------
#define BATCH      512
#define SEQ        64
#define DIM        1024
#define NUM_ACT    8
#define ABINS      256
#define D_STATE    16
#define D_CONV     4
#define D_INNER    2048
#define DT_RANK    64
#define XD         96
#define ROWS       (BATCH * NUM_ACT)        // 4096
#define TABROWS    ((NUM_ACT - 1) * ABINS)  // 1792

// ---------------------------------------------------------------------------
// Scratch (static device allocations; no cudaMalloc allowed)
// ---------------------------------------------------------------------------
__device__ float d_tproj  [TABROWS * 2 * D_INNER];
__device__ float d_sosproj[BATCH * 2 * D_INNER];
__device__ float d_xc     [ROWS * D_INNER];
__device__ float d_xdbl   [ROWS * XD];
__device__ float d_delta  [ROWS * D_INNER];
__device__ float d_embed  [ROWS * DIM];
// bf16 operand copies for the big GEMMs
__device__ __align__(16) __nv_bfloat16 d_sos_bf   [BATCH * DIM];
__device__ __align__(16) __nv_bfloat16 d_tab_bf   [NUM_ACT * ABINS * DIM];
__device__ __align__(16) __nv_bfloat16 d_inproj_bf[2 * D_INNER * DIM];
__device__ __align__(16) __nv_bfloat16 d_outproj_bf[DIM * D_INNER];
__device__ __align__(16) __nv_bfloat16 d_y_bf     [ROWS * D_INNER];

// ---------------------------------------------------------------------------
// Common MMA helpers
// ---------------------------------------------------------------------------
__device__ __forceinline__ void ldsm_x4(unsigned r[4], uint32_t addr) {
    asm volatile("ldmatrix.sync.aligned.m8n8.x4.shared.b16 {%0,%1,%2,%3}, [%4];\n"
                 : "=r"(r[0]), "=r"(r[1]), "=r"(r[2]), "=r"(r[3])
                 : "r"(addr));
}

__device__ __forceinline__ void mma_bf16(float c[4],
                                         const unsigned a[4],
                                         const unsigned b[2]) {
    asm volatile(
        "mma.sync.aligned.m16n8k16.row.col.f32.bf16.bf16.f32 "
        "{%0,%1,%2,%3}, {%4,%5,%6,%7}, {%8,%9}, {%0,%1,%2,%3};\n"
        : "+f"(c[0]), "+f"(c[1]), "+f"(c[2]), "+f"(c[3])
        : "r"(a[0]), "r"(a[1]), "r"(a[2]), "r"(a[3]),
          "r"(b[0]), "r"(b[1]));
}

__device__ __forceinline__ void cp_async16(uint32_t dst, const void* src) {
    asm volatile("cp.async.cg.shared.global [%0], [%1], 16;\n"
                 :: "r"(dst), "l"(src));
}

// ---------------------------------------------------------------------------
// gemm_big: bf16 operands in gmem, fp32 out. C[m,n] = sum_k A[m,k]*B[n,k].
//   Block tile 128x256xBK64, 8 warps (2m x 4n), warp tile 64x64.
//   3-stage cp.async pipeline, one __syncthreads per K-tile.
//   Requirements: M%128==0, N%256==0, K%64==0, lda/ldb%8==0. EPI none.
// ---------------------------------------------------------------------------
#define BM2   128
#define BN2   256
#define BK2   64
#define BKP2  72   // pitch (bf16): 144B = 9x16B -> ldmatrix conflict-free
#define ASTG  (BM2 * BKP2 * 2)     // bytes per A stage (18432)
#define BSTG  (BN2 * BKP2 * 2)     // bytes per B stage (36864)
#define BIG_SMEM (3 * (ASTG + BSTG))   // 165888 B

__global__ __launch_bounds__(256)
void gemm_big(const __nv_bfloat16* __restrict__ A,
              const __nv_bfloat16* __restrict__ B,
              float* __restrict__ C, int M, int N, int K,
              int lda, int ldb, int ldc)
{
    extern __shared__ char smem_raw[];
    const uint32_t sA = (uint32_t)__cvta_generic_to_shared(smem_raw);
    const uint32_t sB = sA + 3 * ASTG;

    const int tid  = threadIdx.x;
    const int warp = tid >> 5;
    const int lane = tid & 31;
    const int wm   = (warp >> 2) * 64;    // 0 or 64
    const int wn   = (warp & 3)  * 64;    // 0,64,128,192
    const int gid  = lane >> 2;
    const int tig  = lane & 3;

    const int bm = blockIdx.y * BM2;
    const int bn = blockIdx.x * BN2;

    // fragment lane offsets (bytes) — R14-verified mappings at pitch BKP2
    const int a_row = (lane & 7) + ((lane >> 3) & 1) * 8;
    const uint32_t a_off = (uint32_t)(a_row * BKP2 + (lane >> 4) * 8) * 2;
    const int b_row = (lane & 7) + ((lane >> 4) ? 8 : 0);
    const uint32_t b_off = (uint32_t)(b_row * BKP2 + ((lane >> 3) & 1) * 8) * 2;

    float acc[4][8][4];
    #pragma unroll
    for (int i = 0; i < 4; i++)
        #pragma unroll
        for (int j = 0; j < 8; j++)
            #pragma unroll
            for (int e = 0; e < 4; e++) acc[i][j][e] = 0.f;

    // stage one 128x64 A + 256x64 B bf16 tile via cp.async (16B chunks)
    auto stage = [&](int it) {
        const int k0 = it * BK2;
        const int s  = it % 3;
        const uint32_t dA = sA + s * ASTG;
        const uint32_t dB = sB + s * BSTG;
        #pragma unroll
        for (int i = 0; i < 4; i++) {                // A: 1024 chunks
            int ci = tid + i * 256;
            int row = ci >> 3, c8 = ci & 7;
            cp_async16(dA + (uint32_t)(row * BKP2 + c8 * 8) * 2,
                       A + (long)(bm + row) * lda + k0 + c8 * 8);
        }
        #pragma unroll
        for (int i = 0; i < 8; i++) {                // B: 2048 chunks
            int ci = tid + i * 256;
            int row = ci >> 3, c8 = ci & 7;
            cp_async16(dB + (uint32_t)(row * BKP2 + c8 * 8) * 2,
                       B + (long)(bn + row) * ldb + k0 + c8 * 8);
        }
    };

    const int nk = K / BK2;    // >= 2 for all call sites
    stage(0);
    asm volatile("cp.async.commit_group;");
    stage(1);
    asm volatile("cp.async.commit_group;");

    for (int it = 0; it < nk; ++it) {
        asm volatile("cp.async.wait_group 1;");
        __syncthreads();                 // stage(it) visible; compute(it-1) done
        if (it + 2 < nk) stage(it + 2);
        asm volatile("cp.async.commit_group;");   // possibly-empty group

        const int s = it % 3;
        const uint32_t aBase = sA + s * ASTG + a_off;
        const uint32_t bBase = sB + s * BSTG + b_off;

        #pragma unroll
        for (int kk = 0; kk < BK2; kk += 16) {
            unsigned a[4][4], b[4][4];
            #pragma unroll
            for (int mt = 0; mt < 4; mt++)
                ldsm_x4(a[mt], aBase + (uint32_t)((wm + mt * 16) * BKP2 + kk) * 2);
            #pragma unroll
            for (int np = 0; np < 4; np++)
                ldsm_x4(b[np], bBase + (uint32_t)((wn + np * 16) * BKP2 + kk) * 2);
            #pragma unroll
            for (int mt = 0; mt < 4; mt++)
                #pragma unroll
                for (int nt = 0; nt < 8; nt++)
                    mma_bf16(acc[mt][nt], a[mt], &b[nt >> 1][(nt & 1) * 2]);
        }
    }

    // epilogue (no guards: all dims divide evenly)
    #pragma unroll
    for (int mt = 0; mt < 4; mt++) {
        int m0 = bm + wm + mt * 16 + gid;
        #pragma unroll
        for (int nt = 0; nt < 8; nt++) {
            int col0 = bn + wn + nt * 8 + tig * 2;
            #pragma unroll
            for (int e = 0; e < 4; e++) {
                int m = m0 + ((e >> 1) ? 8 : 0);
                int n = col0 + (e & 1);
                C[(long)m * ldc + n] = acc[mt][nt][e];
            }
        }
    }
}

// ---------------------------------------------------------------------------
// gemm_bf16 (R14, proven): fp32 in gmem, converts at staging. For small GEMMs.
// ---------------------------------------------------------------------------
#define BM  128
#define BN  128
#define BK  32
#define BKP 40

__device__ __forceinline__ uint4 cvt8_bf16(const float4& a, const float4& b) {
    __nv_bfloat162 p0 = __float22bfloat162_rn(make_float2(a.x, a.y));
    __nv_bfloat162 p1 = __float22bfloat162_rn(make_float2(a.z, a.w));
    __nv_bfloat162 p2 = __float22bfloat162_rn(make_float2(b.x, b.y));
    __nv_bfloat162 p3 = __float22bfloat162_rn(make_float2(b.z, b.w));
    uint4 u;
    u.x = *reinterpret_cast<unsigned*>(&p0);
    u.y = *reinterpret_cast<unsigned*>(&p1);
    u.z = *reinterpret_cast<unsigned*>(&p2);
    u.w = *reinterpret_cast<unsigned*>(&p3);
    return u;
}

template<int EPI>
__global__ __launch_bounds__(256)
void gemm_bf16(const float* __restrict__ Ag, const float* __restrict__ Bg,
               float* __restrict__ Cg, int M, int N, int K,
               int lda, int ldb, int ldc,
               long sAz, long sBz, long sCz,
               const float* __restrict__ bias)
{
    const float* A = Ag + (long)blockIdx.z * sAz;
    const float* B = Bg + (long)blockIdx.z * sBz;
    float*       C = Cg + (long)blockIdx.z * sCz;

    __shared__ alignas(16) __nv_bfloat16 As[2][BM][BKP];
    __shared__ alignas(16) __nv_bfloat16 Bs[2][BN][BKP];

    const int tid  = threadIdx.x;
    const int warp = tid >> 5;
    const int lane = tid & 31;
    const int wm   = (warp >> 2) * 64;
    const int wn   = (warp & 3)  * 32;
    const int gid  = lane >> 2;
    const int tig  = lane & 3;

    const int bm = blockIdx.y * BM;
    const int bn = blockIdx.x * BN;

    const int lr = tid >> 2;
    const int lc = (tid & 3) * 8;

    const uint32_t sA = (uint32_t)__cvta_generic_to_shared(&As[0][0][0]);
    const uint32_t sB = (uint32_t)__cvta_generic_to_shared(&Bs[0][0][0]);
    const uint32_t bufBytes = BM * BKP * 2;

    const int a_row = (lane & 7) + ((lane >> 3) & 1) * 8;
    const uint32_t a_off = (uint32_t)(a_row * BKP + (lane >> 4) * 8) * 2;
    const int b_row = (lane & 7) + ((lane >> 4) ? 8 : 0);
    const uint32_t b_off = (uint32_t)(b_row * BKP + ((lane >> 3) & 1) * 8) * 2;

    float acc[4][4][4];
    #pragma unroll
    for (int i = 0; i < 4; i++)
        #pragma unroll
        for (int j = 0; j < 4; j++)
            #pragma unroll
            for (int e = 0; e < 4; e++) acc[i][j][e] = 0.f;

    float4 av[2][2], bv[2][2];
    const float4 z4 = make_float4(0.f, 0.f, 0.f, 0.f);

    auto load_g = [&](int k0) {
        #pragma unroll
        for (int r = 0; r < 2; r++) {
            int row = lr + r * 64;
            #pragma unroll
            for (int q = 0; q < 2; q++)
                av[r][q] = *reinterpret_cast<const float4*>(
                    A + (long)(bm + row) * lda + k0 + lc + q * 4);
            int brow = bn + row;
            #pragma unroll
            for (int q = 0; q < 2; q++)
                bv[r][q] = (brow < N)
                    ? *reinterpret_cast<const float4*>(
                          B + (long)brow * ldb + k0 + lc + q * 4)
                    : z4;
        }
    };

    auto store_s = [&](int buf) {
        #pragma unroll
        for (int r = 0; r < 2; r++) {
            int row = lr + r * 64;
            *reinterpret_cast<uint4*>(&As[buf][row][lc]) =
                cvt8_bf16(av[r][0], av[r][1]);
            *reinterpret_cast<uint4*>(&Bs[buf][row][lc]) =
                cvt8_bf16(bv[r][0], bv[r][1]);
        }
    };

    const int nk = K / BK;
    load_g(0);
    store_s(0);
    __syncthreads();

    for (int it = 0; it < nk; ++it) {
        if (it + 1 < nk) load_g((it + 1) * BK);
        const int buf = it & 1;
        const uint32_t aBase = sA + buf * bufBytes + a_off;
        const uint32_t bBase = sB + buf * bufBytes + b_off;

        #pragma unroll
        for (int kk = 0; kk < BK; kk += 16) {
            unsigned a[4][4], b[2][4];
            #pragma unroll
            for (int mt = 0; mt < 4; mt++)
                ldsm_x4(a[mt], aBase + (uint32_t)((wm + mt * 16) * BKP + kk) * 2);
            #pragma unroll
            for (int np = 0; np < 2; np++)
                ldsm_x4(b[np], bBase + (uint32_t)((wn + np * 16) * BKP + kk) * 2);
            #pragma unroll
            for (int mt = 0; mt < 4; mt++)
                #pragma unroll
                for (int nt = 0; nt < 4; nt++)
                    mma_bf16(acc[mt][nt], a[mt], &b[nt >> 1][(nt & 1) * 2]);
        }

        if (it + 1 < nk) store_s((it + 1) & 1);
        __syncthreads();
    }

    #pragma unroll
    for (int mt = 0; mt < 4; mt++) {
        int m0 = bm + wm + mt * 16 + gid;
        #pragma unroll
        for (int nt = 0; nt < 4; nt++) {
            int col0 = bn + wn + nt * 8 + tig * 2;
            #pragma unroll
            for (int e = 0; e < 4; e++) {
                int m = m0 + ((e >> 1) ? 8 : 0);
                int n = col0 + (e & 1);
                if (n < N) {
                    float v = acc[mt][nt][e];
                    if (EPI == 1) {
                        v += bias[n];
                        v = fmaxf(v, 0.f) + log1pf(expf(-fabsf(v)));
                    }
                    int nout = n;
                    if (EPI == 2) {
                        nout = (n + 255) & 255;
                        v = 1.f / (1.f + __expf(-v));
                    }
                    C[(long)m * ldc + nout] = v;
                }
            }
        }
    }
}

// ---------------------------------------------------------------------------
// fp32 -> bf16 conversion (n % 4 == 0)
// ---------------------------------------------------------------------------
__global__ void cvt_bf16_kernel(const float* __restrict__ src,
                                __nv_bfloat16* __restrict__ dst, int n)
{
    int i = (blockIdx.x * blockDim.x + threadIdx.x) * 4;
    if (i < n) {
        float4 v = *reinterpret_cast<const float4*>(src + i);
        __nv_bfloat162 p0 = __float22bfloat162_rn(make_float2(v.x, v.y));
        __nv_bfloat162 p1 = __float22bfloat162_rn(make_float2(v.z, v.w));
        uint2 u;
        u.x = *reinterpret_cast<unsigned*>(&p0);
        u.y = *reinterpret_cast<unsigned*>(&p1);
        *reinterpret_cast<uint2*>(dst + i) = u;
    }
}

// ---------------------------------------------------------------------------
// sos = mean over seq; written directly as bf16 (only consumer is sosproj GEMM)
// ---------------------------------------------------------------------------
__global__ void mean_kernel(const float* __restrict__ es,
                            __nv_bfloat16* __restrict__ sos)
{
    int b = blockIdx.x;
    for (int d = threadIdx.x; d < DIM; d += blockDim.x) {
        const float* p = es + (long)b * SEQ * DIM + d;
        float s = 0.f;
        #pragma unroll
        for (int t = 0; t < SEQ; t++) s += p[(long)t * DIM];
        sos[b * DIM + d] = __float2bfloat16(s * (1.f / SEQ));
    }
}

__device__ __forceinline__ const float* xz_row(int b, int t,
                                               const int* __restrict__ actions,
                                               const float* __restrict__ sosproj,
                                               const float* __restrict__ tproj)
{
    if (t == 0) return sosproj + (long)b * (2 * D_INNER);
    int act = actions[b * (NUM_ACT - 1) + (t - 1)];
    return tproj + (long)((t - 1) * ABINS + act) * (2 * D_INNER);
}

// ---------------------------------------------------------------------------
// Causal depthwise conv (D_CONV=4) + SiLU
// ---------------------------------------------------------------------------
__global__ void conv_silu_kernel(const int* __restrict__ actions,
                                 const float* __restrict__ sosproj,
                                 const float* __restrict__ tproj,
                                 const float* __restrict__ conv_w,
                                 const float* __restrict__ conv_b,
                                 float* __restrict__ xc)
{
    int row = blockIdx.x;
    int b = row >> 3, l = row & 7;
    const float* p[4];
    #pragma unroll
    for (int k = 0; k < 4; k++) {
        int t = l + k - 3;
        p[k] = (t >= 0) ? xz_row(b, t, actions, sosproj, tproj) : nullptr;
    }
    for (int c = threadIdx.x; c < D_INNER; c += blockDim.x) {
        float a = conv_b[c];
        #pragma unroll
        for (int k = 0; k < 4; k++)
            if (p[k]) a = fmaf(p[k][c], conv_w[c * 4 + k], a);
        xc[(long)row * D_INNER + c] = a / (1.f + __expf(-a));
    }
}

// ---------------------------------------------------------------------------
// Selective scan + skip + SiLU(z) gate; writes y as bf16 (embed GEMM input)
// ---------------------------------------------------------------------------
__global__ void scan_kernel(const float* __restrict__ xc,
                            const float* __restrict__ delta,
                            const float* __restrict__ xdbl,
                            const int*   __restrict__ actions,
                            const float* __restrict__ sosproj,
                            const float* __restrict__ tproj,
                            const float* __restrict__ A_log,
                            const float* __restrict__ Dp,
                            __nv_bfloat16* __restrict__ y)
{
    int b = blockIdx.x;
    int tid = threadIdx.x;

    __shared__ float Bs[NUM_ACT][D_STATE];
    __shared__ float Cs[NUM_ACT][D_STATE];
    if (tid < NUM_ACT * D_STATE) {
        int l = tid / D_STATE, n = tid % D_STATE;
        const float* r = xdbl + (long)(b * NUM_ACT + l) * XD;
        Bs[l][n] = r[DT_RANK + n];
        Cs[l][n] = r[DT_RANK + D_STATE + n];
    }
    __syncthreads();

    const float* zp[NUM_ACT];
    #pragma unroll
    for (int l = 0; l < NUM_ACT; l++)
        zp[l] = xz_row(b, l, actions, sosproj, tproj) + D_INNER;

    for (int j = 0; j < D_INNER / 256; j++) {
        int d = tid + j * 256;
        float Arow[D_STATE];
        #pragma unroll
        for (int n = 0; n < D_STATE; n++)
            Arow[n] = -__expf(A_log[d * D_STATE + n]);
        float Dd = Dp[d];
        float h[D_STATE];
        #pragma unroll
        for (int n = 0; n < D_STATE; n++) h[n] = 0.f;

        #pragma unroll
        for (int l = 0; l < NUM_ACT; l++) {
            long row = (long)(b * NUM_ACT + l);
            float dl = delta[row * D_INNER + d];
            float u  = xc[row * D_INNER + d];
            float du = dl * u;
            float yv = 0.f;
            #pragma unroll
            for (int n = 0; n < D_STATE; n++) {
                float dA = __expf(dl * Arow[n]);
                h[n] = fmaf(dA, h[n], du * Bs[l][n]);
                yv   = fmaf(h[n], Cs[l][n], yv);
            }
            yv = fmaf(u, Dd, yv);
            float z = zp[l][d];
            float sz = z / (1.f + __expf(-z));
            y[row * D_INNER + d] = __float2bfloat16(yv * sz);
        }
    }
}

// ---------------------------------------------------------------------------
// Launch
// ---------------------------------------------------------------------------
extern "C" void kernel_launch(void* const* d_in, const int* in_sizes, int n_in,
                              void* d_out, int out_size)
{
    const float* encoded_state = (const float*)d_in[0];
    const int*   actions       = (const int*)  d_in[1];
    const float* tab           = (const float*)d_in[2];   // [8,256,1024]
    /* d_in[3] = gamma (unused by reference) */
    const float* in_proj_w     = (const float*)d_in[4];   // [4096,1024]
    const float* conv_w        = (const float*)d_in[5];
    const float* conv_b        = (const float*)d_in[6];
    const float* x_proj_w      = (const float*)d_in[7];   // [96,2048]
    const float* dt_proj_w     = (const float*)d_in[8];   // [2048,64]
    const float* dt_proj_b     = (const float*)d_in[9];
    const float* A_log         = (const float*)d_in[10];
    const float* D_param       = (const float*)d_in[11];
    const float* out_proj_w    = (const float*)d_in[12];  // [1024,2048]
    float* out = (float*)d_out;                           // [512,8,256]

    float *g_tproj, *g_sosproj, *g_xc, *g_xdbl, *g_delta, *g_embed;
    __nv_bfloat16 *g_sos_bf, *g_tab_bf, *g_inproj_bf, *g_outproj_bf, *g_y_bf;
    cudaGetSymbolAddress((void**)&g_tproj,      d_tproj);
    cudaGetSymbolAddress((void**)&g_sosproj,    d_sosproj);
    cudaGetSymbolAddress((void**)&g_xc,         d_xc);
    cudaGetSymbolAddress((void**)&g_xdbl,       d_xdbl);
    cudaGetSymbolAddress((void**)&g_delta,      d_delta);
    cudaGetSymbolAddress((void**)&g_embed,      d_embed);
    cudaGetSymbolAddress((void**)&g_sos_bf,     d_sos_bf);
    cudaGetSymbolAddress((void**)&g_tab_bf,     d_tab_bf);
    cudaGetSymbolAddress((void**)&g_inproj_bf,  d_inproj_bf);
    cudaGetSymbolAddress((void**)&g_outproj_bf, d_outproj_bf);
    cudaGetSymbolAddress((void**)&g_y_bf,       d_y_bf);

    cudaFuncSetAttribute(gemm_big, cudaFuncAttributeMaxDynamicSharedMemorySize,
                         BIG_SMEM);

    // 0) operand conversions to bf16
    const int n_tab = NUM_ACT * ABINS * DIM;
    const int n_inp = 2 * D_INNER * DIM;
    const int n_out = DIM * D_INNER;
    cvt_bf16_kernel<<<n_tab / 4 / 256, 256>>>(tab, g_tab_bf, n_tab);
    cvt_bf16_kernel<<<n_inp / 4 / 256, 256>>>(in_proj_w, g_inproj_bf, n_inp);
    cvt_bf16_kernel<<<n_out / 4 / 256, 256>>>(out_proj_w, g_outproj_bf, n_out);

    // 1) sos = mean(encoded_state) -> bf16
    mean_kernel<<<BATCH, 256>>>(encoded_state, g_sos_bf);

    // 2) tproj = bin_table[0:1792] @ in_proj^T  (1792 x 4096, K=1024)
    gemm_big<<<dim3(2 * D_INNER / BN2, TABROWS / BM2, 1), 256, BIG_SMEM>>>(
        g_tab_bf, g_inproj_bf, g_tproj, TABROWS, 2 * D_INNER, DIM,
        DIM, DIM, 2 * D_INNER);

    // 3) sosproj = sos @ in_proj^T  (512 x 4096, K=1024)
    gemm_big<<<dim3(2 * D_INNER / BN2, BATCH / BM2, 1), 256, BIG_SMEM>>>(
        g_sos_bf, g_inproj_bf, g_sosproj, BATCH, 2 * D_INNER, DIM,
        DIM, DIM, 2 * D_INNER);

    // 4) xc = silu(causal_conv(xh))
    conv_silu_kernel<<<ROWS, 256>>>(actions, g_sosproj, g_tproj,
                                    conv_w, conv_b, g_xc);

    // 5) x_dbl = xc @ x_proj^T  (4096 x 96, K=2048)
    gemm_bf16<0><<<dim3(1, ROWS / BM, 1), 256>>>(
        g_xc, x_proj_w, g_xdbl, ROWS, XD, D_INNER,
        D_INNER, D_INNER, XD, 0, 0, 0, nullptr);

    // 6) delta = softplus(dt @ dt_proj^T + b)  (4096 x 2048, K=64)
    gemm_bf16<1><<<dim3(D_INNER / BN, ROWS / BM, 1), 256>>>(
        g_xdbl, dt_proj_w, g_delta, ROWS, D_INNER, DT_RANK,
        XD, DT_RANK, D_INNER, 0, 0, 0, dt_proj_b);

    // 7) selective scan -> y (bf16)
    scan_kernel<<<BATCH, 256>>>(g_xc, g_delta, g_xdbl, actions,
                                g_sosproj, g_tproj, A_log, D_param, g_y_bf);

    // 8) embed = y @ out_proj^T  (4096 x 1024, K=2048)
    gemm_big<<<dim3(DIM / BN2, ROWS / BM2, 1), 256, BIG_SMEM>>>(
        g_y_bf, g_outproj_bf, g_embed, ROWS, DIM, D_INNER,
        D_INNER, D_INNER, DIM);

    // 9) out[b,n,a] = sigmoid(embed . tab[n, (a+1)%256])
    gemm_bf16<2><<<dim3(ABINS / BN, BATCH / BM, NUM_ACT), 256>>>(
        g_embed, tab, out, BATCH, ABINS, DIM,
        NUM_ACT * DIM, DIM, NUM_ACT * ABINS,
        DIM, (long)ABINS * DIM, ABINS,
        nullptr);
}

// round 16
// speedup vs baseline: 1.8530x; 1.0016x over previous
#include <cuda_runtime.h>
#include <cuda_bf16.h>
#include <math.h>
#include <stdint.h>

// ---------------------------------------------------------------------------
// Problem constants
// ---------------------------------------------------------------------------
#define BATCH      512
#define SEQ        64
#define DIM        1024
#define NUM_ACT    8
#define ABINS      256
#define D_STATE    16
#define D_CONV     4
#define D_INNER    2048
#define DT_RANK    64
#define XD         96
#define ROWS       (BATCH * NUM_ACT)        // 4096
#define TABROWS    ((NUM_ACT - 1) * ABINS)  // 1792
#define INROWS     (TABROWS + BATCH)        // 2304 combined in_proj A rows

// ---------------------------------------------------------------------------
// Scratch (static device allocations; no cudaMalloc allowed)
// ---------------------------------------------------------------------------
__device__ float d_xzproj [INROWS * 2 * D_INNER];   // rows: [0,1792)=tproj, [1792,2304)=sosproj
__device__ float d_xc     [ROWS * D_INNER];
__device__ float d_delta  [ROWS * D_INNER];
__device__ float d_embed  [ROWS * DIM];
__device__ __align__(16) __nv_bfloat16 d_inA_bf   [INROWS * DIM];      // tab(1792) + sos(512)
__device__ __align__(16) __nv_bfloat16 d_inproj_bf[2 * D_INNER * DIM];
__device__ __align__(16) __nv_bfloat16 d_outproj_bf[DIM * D_INNER];
__device__ __align__(16) __nv_bfloat16 d_dtproj_bf[D_INNER * DT_RANK];
__device__ __align__(16) __nv_bfloat16 d_xdbl_bf  [ROWS * XD];
__device__ __align__(16) __nv_bfloat16 d_y_bf     [ROWS * D_INNER];

// ---------------------------------------------------------------------------
// Common MMA helpers
// ---------------------------------------------------------------------------
__device__ __forceinline__ void ldsm_x4(unsigned r[4], uint32_t addr) {
    asm volatile("ldmatrix.sync.aligned.m8n8.x4.shared.b16 {%0,%1,%2,%3}, [%4];\n"
                 : "=r"(r[0]), "=r"(r[1]), "=r"(r[2]), "=r"(r[3])
                 : "r"(addr));
}

__device__ __forceinline__ void mma_bf16(float c[4],
                                         const unsigned a[4],
                                         const unsigned b[2]) {
    asm volatile(
        "mma.sync.aligned.m16n8k16.row.col.f32.bf16.bf16.f32 "
        "{%0,%1,%2,%3}, {%4,%5,%6,%7}, {%8,%9}, {%0,%1,%2,%3};\n"
        : "+f"(c[0]), "+f"(c[1]), "+f"(c[2]), "+f"(c[3])
        : "r"(a[0]), "r"(a[1]), "r"(a[2]), "r"(a[3]),
          "r"(b[0]), "r"(b[1]));
}

__device__ __forceinline__ void cp_async16(uint32_t dst, const void* src) {
    asm volatile("cp.async.cg.shared.global [%0], [%1], 16;\n"
                 :: "r"(dst), "l"(src));
}

// ---------------------------------------------------------------------------
// gemm_big: bf16 operands in gmem, fp32 out. C[m,n] = sum_k A[m,k]*B[n,k].
//   Block tile 128x256xBK64, 8 warps (2m x 4n), warp tile 64x64.
//   3-stage cp.async pipeline, one __syncthreads per K-tile. Supports nk==1.
//   Requirements: M%128==0, N%256==0, K%64==0, lda/ldb%8==0.
//   EPI: 0 none | 1 softplus(x + bias[n])
// ---------------------------------------------------------------------------
#define BM2   128
#define BN2   256
#define BK2   64
#define BKP2  72   // pitch (bf16): 144B = 9x16B -> ldmatrix conflict-free
#define ASTG  (BM2 * BKP2 * 2)
#define BSTG  (BN2 * BKP2 * 2)
#define BIG_SMEM (3 * (ASTG + BSTG))   // 165888 B

template<int EPI>
__global__ __launch_bounds__(256)
void gemm_big(const __nv_bfloat16* __restrict__ A,
              const __nv_bfloat16* __restrict__ B,
              float* __restrict__ C, int M, int N, int K,
              int lda, int ldb, int ldc,
              const float* __restrict__ bias)
{
    extern __shared__ char smem_raw[];
    const uint32_t sA = (uint32_t)__cvta_generic_to_shared(smem_raw);
    const uint32_t sB = sA + 3 * ASTG;

    const int tid  = threadIdx.x;
    const int warp = tid >> 5;
    const int lane = tid & 31;
    const int wm   = (warp >> 2) * 64;
    const int wn   = (warp & 3)  * 64;
    const int gid  = lane >> 2;
    const int tig  = lane & 3;

    const int bm = blockIdx.y * BM2;
    const int bn = blockIdx.x * BN2;

    const int a_row = (lane & 7) + ((lane >> 3) & 1) * 8;
    const uint32_t a_off = (uint32_t)(a_row * BKP2 + (lane >> 4) * 8) * 2;
    const int b_row = (lane & 7) + ((lane >> 4) ? 8 : 0);
    const uint32_t b_off = (uint32_t)(b_row * BKP2 + ((lane >> 3) & 1) * 8) * 2;

    float acc[4][8][4];
    #pragma unroll
    for (int i = 0; i < 4; i++)
        #pragma unroll
        for (int j = 0; j < 8; j++)
            #pragma unroll
            for (int e = 0; e < 4; e++) acc[i][j][e] = 0.f;

    auto stage = [&](int it) {
        const int k0 = it * BK2;
        const int s  = it % 3;
        const uint32_t dA = sA + s * ASTG;
        const uint32_t dB = sB + s * BSTG;
        #pragma unroll
        for (int i = 0; i < 4; i++) {
            int ci = tid + i * 256;
            int row = ci >> 3, c8 = ci & 7;
            cp_async16(dA + (uint32_t)(row * BKP2 + c8 * 8) * 2,
                       A + (long)(bm + row) * lda + k0 + c8 * 8);
        }
        #pragma unroll
        for (int i = 0; i < 8; i++) {
            int ci = tid + i * 256;
            int row = ci >> 3, c8 = ci & 7;
            cp_async16(dB + (uint32_t)(row * BKP2 + c8 * 8) * 2,
                       B + (long)(bn + row) * ldb + k0 + c8 * 8);
        }
    };

    const int nk = K / BK2;
    stage(0);
    asm volatile("cp.async.commit_group;");
    if (nk > 1) stage(1);
    asm volatile("cp.async.commit_group;");

    for (int it = 0; it < nk; ++it) {
        asm volatile("cp.async.wait_group 1;");
        __syncthreads();
        if (it + 2 < nk) stage(it + 2);
        asm volatile("cp.async.commit_group;");

        const int s = it % 3;
        const uint32_t aBase = sA + s * ASTG + a_off;
        const uint32_t bBase = sB + s * BSTG + b_off;

        #pragma unroll
        for (int kk = 0; kk < BK2; kk += 16) {
            unsigned a[4][4], b[4][4];
            #pragma unroll
            for (int mt = 0; mt < 4; mt++)
                ldsm_x4(a[mt], aBase + (uint32_t)((wm + mt * 16) * BKP2 + kk) * 2);
            #pragma unroll
            for (int np = 0; np < 4; np++)
                ldsm_x4(b[np], bBase + (uint32_t)((wn + np * 16) * BKP2 + kk) * 2);
            #pragma unroll
            for (int mt = 0; mt < 4; mt++)
                #pragma unroll
                for (int nt = 0; nt < 8; nt++)
                    mma_bf16(acc[mt][nt], a[mt], &b[nt >> 1][(nt & 1) * 2]);
        }
    }

    #pragma unroll
    for (int mt = 0; mt < 4; mt++) {
        int m0 = bm + wm + mt * 16 + gid;
        #pragma unroll
        for (int nt = 0; nt < 8; nt++) {
            int col0 = bn + wn + nt * 8 + tig * 2;
            #pragma unroll
            for (int e = 0; e < 4; e++) {
                int m = m0 + ((e >> 1) ? 8 : 0);
                int n = col0 + (e & 1);
                float v = acc[mt][nt][e];
                if (EPI == 1) {
                    v += bias[n];
                    v = fmaxf(v, 0.f) + log1pf(expf(-fabsf(v)));
                }
                C[(long)m * ldc + n] = v;
            }
        }
    }
}

// ---------------------------------------------------------------------------
// gemm_bf16 (proven): fp32 in gmem, converts at staging. Small GEMMs.
//   OUT: 0 = fp32 C, 1 = bf16 C
// ---------------------------------------------------------------------------
#define BM  128
#define BN  128
#define BK  32
#define BKP 40

__device__ __forceinline__ uint4 cvt8_bf16(const float4& a, const float4& b) {
    __nv_bfloat162 p0 = __float22bfloat162_rn(make_float2(a.x, a.y));
    __nv_bfloat162 p1 = __float22bfloat162_rn(make_float2(a.z, a.w));
    __nv_bfloat162 p2 = __float22bfloat162_rn(make_float2(b.x, b.y));
    __nv_bfloat162 p3 = __float22bfloat162_rn(make_float2(b.z, b.w));
    uint4 u;
    u.x = *reinterpret_cast<unsigned*>(&p0);
    u.y = *reinterpret_cast<unsigned*>(&p1);
    u.z = *reinterpret_cast<unsigned*>(&p2);
    u.w = *reinterpret_cast<unsigned*>(&p3);
    return u;
}

template<int EPI, int OUT>
__global__ __launch_bounds__(256)
void gemm_bf16(const float* __restrict__ Ag, const float* __restrict__ Bg,
               void* __restrict__ Cg, int M, int N, int K,
               int lda, int ldb, int ldc,
               long sAz, long sBz, long sCz,
               const float* __restrict__ bias)
{
    const float* A = Ag + (long)blockIdx.z * sAz;
    const float* B = Bg + (long)blockIdx.z * sBz;
    float*         Cf = (float*)Cg + (long)blockIdx.z * sCz;
    __nv_bfloat16* Cb = (__nv_bfloat16*)Cg + (long)blockIdx.z * sCz;

    __shared__ alignas(16) __nv_bfloat16 As[2][BM][BKP];
    __shared__ alignas(16) __nv_bfloat16 Bs[2][BN][BKP];

    const int tid  = threadIdx.x;
    const int warp = tid >> 5;
    const int lane = tid & 31;
    const int wm   = (warp >> 2) * 64;
    const int wn   = (warp & 3)  * 32;
    const int gid  = lane >> 2;
    const int tig  = lane & 3;

    const int bm = blockIdx.y * BM;
    const int bn = blockIdx.x * BN;

    const int lr = tid >> 2;
    const int lc = (tid & 3) * 8;

    const uint32_t sA = (uint32_t)__cvta_generic_to_shared(&As[0][0][0]);
    const uint32_t sB = (uint32_t)__cvta_generic_to_shared(&Bs[0][0][0]);
    const uint32_t bufBytes = BM * BKP * 2;

    const int a_row = (lane & 7) + ((lane >> 3) & 1) * 8;
    const uint32_t a_off = (uint32_t)(a_row * BKP + (lane >> 4) * 8) * 2;
    const int b_row = (lane & 7) + ((lane >> 4) ? 8 : 0);
    const uint32_t b_off = (uint32_t)(b_row * BKP + ((lane >> 3) & 1) * 8) * 2;

    float acc[4][4][4];
    #pragma unroll
    for (int i = 0; i < 4; i++)
        #pragma unroll
        for (int j = 0; j < 4; j++)
            #pragma unroll
            for (int e = 0; e < 4; e++) acc[i][j][e] = 0.f;

    float4 av[2][2], bv[2][2];
    const float4 z4 = make_float4(0.f, 0.f, 0.f, 0.f);

    auto load_g = [&](int k0) {
        #pragma unroll
        for (int r = 0; r < 2; r++) {
            int row = lr + r * 64;
            #pragma unroll
            for (int q = 0; q < 2; q++)
                av[r][q] = *reinterpret_cast<const float4*>(
                    A + (long)(bm + row) * lda + k0 + lc + q * 4);
            int brow = bn + row;
            #pragma unroll
            for (int q = 0; q < 2; q++)
                bv[r][q] = (brow < N)
                    ? *reinterpret_cast<const float4*>(
                          B + (long)brow * ldb + k0 + lc + q * 4)
                    : z4;
        }
    };

    auto store_s = [&](int buf) {
        #pragma unroll
        for (int r = 0; r < 2; r++) {
            int row = lr + r * 64;
            *reinterpret_cast<uint4*>(&As[buf][row][lc]) =
                cvt8_bf16(av[r][0], av[r][1]);
            *reinterpret_cast<uint4*>(&Bs[buf][row][lc]) =
                cvt8_bf16(bv[r][0], bv[r][1]);
        }
    };

    const int nk = K / BK;
    load_g(0);
    store_s(0);
    __syncthreads();

    for (int it = 0; it < nk; ++it) {
        if (it + 1 < nk) load_g((it + 1) * BK);
        const int buf = it & 1;
        const uint32_t aBase = sA + buf * bufBytes + a_off;
        const uint32_t bBase = sB + buf * bufBytes + b_off;

        #pragma unroll
        for (int kk = 0; kk < BK; kk += 16) {
            unsigned a[4][4], b[2][4];
            #pragma unroll
            for (int mt = 0; mt < 4; mt++)
                ldsm_x4(a[mt], aBase + (uint32_t)((wm + mt * 16) * BKP + kk) * 2);
            #pragma unroll
            for (int np = 0; np < 2; np++)
                ldsm_x4(b[np], bBase + (uint32_t)((wn + np * 16) * BKP + kk) * 2);
            #pragma unroll
            for (int mt = 0; mt < 4; mt++)
                #pragma unroll
                for (int nt = 0; nt < 4; nt++)
                    mma_bf16(acc[mt][nt], a[mt], &b[nt >> 1][(nt & 1) * 2]);
        }

        if (it + 1 < nk) store_s((it + 1) & 1);
        __syncthreads();
    }

    #pragma unroll
    for (int mt = 0; mt < 4; mt++) {
        int m0 = bm + wm + mt * 16 + gid;
        #pragma unroll
        for (int nt = 0; nt < 4; nt++) {
            int col0 = bn + wn + nt * 8 + tig * 2;
            #pragma unroll
            for (int e = 0; e < 4; e++) {
                int m = m0 + ((e >> 1) ? 8 : 0);
                int n = col0 + (e & 1);
                if (n < N) {
                    float v = acc[mt][nt][e];
                    if (EPI == 1) {
                        v += bias[n];
                        v = fmaxf(v, 0.f) + log1pf(expf(-fabsf(v)));
                    }
                    int nout = n;
                    if (EPI == 2) {
                        nout = (n + 255) & 255;
                        v = 1.f / (1.f + __expf(-v));
                    }
                    if (OUT == 1)
                        Cb[(long)m * ldc + nout] = __float2bfloat16(v);
                    else
                        Cf[(long)m * ldc + nout] = v;
                }
            }
        }
    }
}

// ---------------------------------------------------------------------------
// fp32 -> bf16 conversion (n % 4 == 0)
// ---------------------------------------------------------------------------
__global__ void cvt_bf16_kernel(const float* __restrict__ src,
                                __nv_bfloat16* __restrict__ dst, int n)
{
    int i = (blockIdx.x * blockDim.x + threadIdx.x) * 4;
    if (i < n) {
        float4 v = *reinterpret_cast<const float4*>(src + i);
        __nv_bfloat162 p0 = __float22bfloat162_rn(make_float2(v.x, v.y));
        __nv_bfloat162 p1 = __float22bfloat162_rn(make_float2(v.z, v.w));
        uint2 u;
        u.x = *reinterpret_cast<unsigned*>(&p0);
        u.y = *reinterpret_cast<unsigned*>(&p1);
        *reinterpret_cast<uint2*>(dst + i) = u;
    }
}

// ---------------------------------------------------------------------------
// sos mean (float4), written as bf16 into combined in-proj A at row 1792+b
// ---------------------------------------------------------------------------
__global__ void mean_kernel(const float* __restrict__ es,
                            __nv_bfloat16* __restrict__ dst)
{
    int b = blockIdx.x;
    int d4 = threadIdx.x;                       // 256 threads * 4 = 1024
    const float4* p = reinterpret_cast<const float4*>(es + (long)b * SEQ * DIM) + d4;
    float4 s = make_float4(0.f, 0.f, 0.f, 0.f);
    #pragma unroll
    for (int t = 0; t < SEQ; t++) {
        float4 v = p[t * (DIM / 4)];
        s.x += v.x; s.y += v.y; s.z += v.z; s.w += v.w;
    }
    const float r = 1.f / SEQ;
    __nv_bfloat162 p0 = __float22bfloat162_rn(make_float2(s.x * r, s.y * r));
    __nv_bfloat162 p1 = __float22bfloat162_rn(make_float2(s.z * r, s.w * r));
    uint2 u;
    u.x = *reinterpret_cast<unsigned*>(&p0);
    u.y = *reinterpret_cast<unsigned*>(&p1);
    *reinterpret_cast<uint2*>(dst + (long)(TABROWS + b) * DIM + d4 * 4) = u;
}

// Row of the (virtual) xz matrix for (batch b, token t) in d_xzproj
__device__ __forceinline__ const float* xz_row(int b, int t,
                                               const int* __restrict__ actions,
                                               const float* __restrict__ xzproj)
{
    int row = (t == 0) ? (TABROWS + b)
                       : ((t - 1) * ABINS + actions[b * (NUM_ACT - 1) + (t - 1)]);
    return xzproj + (long)row * (2 * D_INNER);
}

// ---------------------------------------------------------------------------
// Causal depthwise conv (D_CONV=4) + SiLU, float4. One block per token row.
// ---------------------------------------------------------------------------
__global__ void conv_silu_kernel(const int* __restrict__ actions,
                                 const float* __restrict__ xzproj,
                                 const float* __restrict__ conv_w,
                                 const float* __restrict__ conv_b,
                                 float* __restrict__ xc)
{
    int row = blockIdx.x;
    int b = row >> 3, l = row & 7;
    const float4* p[4];
    #pragma unroll
    for (int k = 0; k < 4; k++) {
        int t = l + k - 3;
        p[k] = (t >= 0)
             ? reinterpret_cast<const float4*>(xz_row(b, t, actions, xzproj))
             : nullptr;
    }
    for (int c4 = threadIdx.x; c4 < D_INNER / 4; c4 += blockDim.x) {
        float4 acc = reinterpret_cast<const float4*>(conv_b)[c4];
        float* a = &acc.x;
        #pragma unroll
        for (int k = 0; k < 4; k++) {
            if (!p[k]) continue;
            float4 v = p[k][c4];
            const float* vv = &v.x;
            #pragma unroll
            for (int j = 0; j < 4; j++)
                a[j] = fmaf(vv[j], conv_w[(c4 * 4 + j) * 4 + k], a[j]);
        }
        float4 o;
        o.x = acc.x / (1.f + __expf(-acc.x));
        o.y = acc.y / (1.f + __expf(-acc.y));
        o.z = acc.z / (1.f + __expf(-acc.z));
        o.w = acc.w / (1.f + __expf(-acc.w));
        reinterpret_cast<float4*>(xc + (long)row * D_INNER)[c4] = o;
    }
}

// ---------------------------------------------------------------------------
// Selective scan + skip + SiLU(z) gate; xdbl in bf16; writes y as bf16
// ---------------------------------------------------------------------------
__global__ void scan_kernel(const float* __restrict__ xc,
                            const float* __restrict__ delta,
                            const __nv_bfloat16* __restrict__ xdbl,
                            const int*   __restrict__ actions,
                            const float* __restrict__ xzproj,
                            const float* __restrict__ A_log,
                            const float* __restrict__ Dp,
                            __nv_bfloat16* __restrict__ y)
{
    int b = blockIdx.x;
    int tid = threadIdx.x;

    __shared__ float Bs[NUM_ACT][D_STATE];
    __shared__ float Cs[NUM_ACT][D_STATE];
    if (tid < NUM_ACT * D_STATE) {
        int l = tid / D_STATE, n = tid % D_STATE;
        const __nv_bfloat16* r = xdbl + (long)(b * NUM_ACT + l) * XD;
        Bs[l][n] = __bfloat162float(r[DT_RANK + n]);
        Cs[l][n] = __bfloat162float(r[DT_RANK + D_STATE + n]);
    }
    __syncthreads();

    const float* zp[NUM_ACT];
    #pragma unroll
    for (int l = 0; l < NUM_ACT; l++)
        zp[l] = xz_row(b, l, actions, xzproj) + D_INNER;

    for (int j = 0; j < D_INNER / 256; j++) {
        int d = tid + j * 256;
        float Arow[D_STATE];
        #pragma unroll
        for (int n = 0; n < D_STATE; n++)
            Arow[n] = -__expf(A_log[d * D_STATE + n]);
        float Dd = Dp[d];
        float h[D_STATE];
        #pragma unroll
        for (int n = 0; n < D_STATE; n++) h[n] = 0.f;

        #pragma unroll
        for (int l = 0; l < NUM_ACT; l++) {
            long row = (long)(b * NUM_ACT + l);
            float dl = delta[row * D_INNER + d];
            float u  = xc[row * D_INNER + d];
            float du = dl * u;
            float yv = 0.f;
            #pragma unroll
            for (int n = 0; n < D_STATE; n++) {
                float dA = __expf(dl * Arow[n]);
                h[n] = fmaf(dA, h[n], du * Bs[l][n]);
                yv   = fmaf(h[n], Cs[l][n], yv);
            }
            yv = fmaf(u, Dd, yv);
            float z = zp[l][d];
            float sz = z / (1.f + __expf(-z));
            y[row * D_INNER + d] = __float2bfloat16(yv * sz);
        }
    }
}

// ---------------------------------------------------------------------------
// Launch
// ---------------------------------------------------------------------------
extern "C" void kernel_launch(void* const* d_in, const int* in_sizes, int n_in,
                              void* d_out, int out_size)
{
    const float* encoded_state = (const float*)d_in[0];
    const int*   actions       = (const int*)  d_in[1];
    const float* tab           = (const float*)d_in[2];   // [8,256,1024]
    /* d_in[3] = gamma (unused by reference) */
    const float* in_proj_w     = (const float*)d_in[4];   // [4096,1024]
    const float* conv_w        = (const float*)d_in[5];
    const float* conv_b        = (const float*)d_in[6];
    const float* x_proj_w      = (const float*)d_in[7];   // [96,2048]
    const float* dt_proj_w     = (const float*)d_in[8];   // [2048,64]
    const float* dt_proj_b     = (const float*)d_in[9];
    const float* A_log         = (const float*)d_in[10];
    const float* D_param       = (const float*)d_in[11];
    const float* out_proj_w    = (const float*)d_in[12];  // [1024,2048]
    float* out = (float*)d_out;                           // [512,8,256]

    float *g_xzproj, *g_xc, *g_delta, *g_embed;
    __nv_bfloat16 *g_inA_bf, *g_inproj_bf, *g_outproj_bf, *g_dtproj_bf,
                  *g_xdbl_bf, *g_y_bf;
    cudaGetSymbolAddress((void**)&g_xzproj,     d_xzproj);
    cudaGetSymbolAddress((void**)&g_xc,         d_xc);
    cudaGetSymbolAddress((void**)&g_delta,      d_delta);
    cudaGetSymbolAddress((void**)&g_embed,      d_embed);
    cudaGetSymbolAddress((void**)&g_inA_bf,     d_inA_bf);
    cudaGetSymbolAddress((void**)&g_inproj_bf,  d_inproj_bf);
    cudaGetSymbolAddress((void**)&g_outproj_bf, d_outproj_bf);
    cudaGetSymbolAddress((void**)&g_dtproj_bf,  d_dtproj_bf);
    cudaGetSymbolAddress((void**)&g_xdbl_bf,    d_xdbl_bf);
    cudaGetSymbolAddress((void**)&g_y_bf,       d_y_bf);

    cudaFuncSetAttribute(gemm_big<0>, cudaFuncAttributeMaxDynamicSharedMemorySize,
                         BIG_SMEM);
    cudaFuncSetAttribute(gemm_big<1>, cudaFuncAttributeMaxDynamicSharedMemorySize,
                         BIG_SMEM);

    // 0) operand conversions to bf16
    const int n_tab = TABROWS * DIM;          // only first 1792 rows needed
    const int n_inp = 2 * D_INNER * DIM;
    const int n_out = DIM * D_INNER;
    const int n_dtp = D_INNER * DT_RANK;
    cvt_bf16_kernel<<<n_tab / 4 / 256, 256>>>(tab, g_inA_bf, n_tab);
    cvt_bf16_kernel<<<n_inp / 4 / 256, 256>>>(in_proj_w, g_inproj_bf, n_inp);
    cvt_bf16_kernel<<<n_out / 4 / 256, 256>>>(out_proj_w, g_outproj_bf, n_out);
    cvt_bf16_kernel<<<n_dtp / 4 / 256, 256>>>(dt_proj_w, g_dtproj_bf, n_dtp);

    // 1) sos = mean(encoded_state) -> bf16 rows [1792, 2304) of inA
    mean_kernel<<<BATCH, 256>>>(encoded_state, g_inA_bf);

    // 2) xzproj = [tab(1792) ; sos(512)] @ in_proj^T  (2304 x 4096, K=1024)
    gemm_big<0><<<dim3(2 * D_INNER / BN2, INROWS / BM2, 1), 256, BIG_SMEM>>>(
        g_inA_bf, g_inproj_bf, g_xzproj, INROWS, 2 * D_INNER, DIM,
        DIM, DIM, 2 * D_INNER, nullptr);

    // 3) xc = silu(causal_conv(xh))
    conv_silu_kernel<<<ROWS, 256>>>(actions, g_xzproj, conv_w, conv_b, g_xc);

    // 4) x_dbl = xc @ x_proj^T  (4096 x 96, K=2048) -> bf16
    gemm_bf16<0, 1><<<dim3(1, ROWS / BM, 1), 256>>>(
        g_xc, x_proj_w, g_xdbl_bf, ROWS, XD, D_INNER,
        D_INNER, D_INNER, XD, 0, 0, 0, nullptr);

    // 5) delta = softplus(dt @ dt_proj^T + b)  (4096 x 2048, K=64)
    gemm_big<1><<<dim3(D_INNER / BN2, ROWS / BM2, 1), 256, BIG_SMEM>>>(
        g_xdbl_bf, g_dtproj_bf, g_delta, ROWS, D_INNER, DT_RANK,
        XD, DT_RANK, D_INNER, dt_proj_b);

    // 6) selective scan -> y (bf16)
    scan_kernel<<<BATCH, 256>>>(g_xc, g_delta, g_xdbl_bf, actions,
                                g_xzproj, A_log, D_param, g_y_bf);

    // 7) embed = y @ out_proj^T  (4096 x 1024, K=2048)
    gemm_big<0><<<dim3(DIM / BN2, ROWS / BM2, 1), 256, BIG_SMEM>>>(
        g_y_bf, g_outproj_bf, g_embed, ROWS, DIM, D_INNER,
        D_INNER, D_INNER, DIM, nullptr);

    // 8) out[b,n,a] = sigmoid(embed . tab[n, (a+1)%256])
    gemm_bf16<2, 0><<<dim3(ABINS / BN, BATCH / BM, NUM_ACT), 256>>>(
        g_embed, tab, out, BATCH, ABINS, DIM,
        NUM_ACT * DIM, DIM, NUM_ACT * ABINS,
        DIM, (long)ABINS * DIM, ABINS,
        nullptr);
}

// round 17
// speedup vs baseline: 1.9151x; 1.0335x over previous
#include <cuda_runtime.h>
#include <cuda_bf16.h>
#include <math.h>
#include <stdint.h>

// ---------------------------------------------------------------------------
// Problem constants
// ---------------------------------------------------------------------------
#define BATCH      512
#define SEQ        64
#define DIM        1024
#define NUM_ACT    8
#define ABINS      256
#define D_STATE    16
#define D_CONV     4
#define D_INNER    2048
#define DT_RANK    64
#define XD         96
#define ROWS       (BATCH * NUM_ACT)        // 4096
#define TABROWS    ((NUM_ACT - 1) * ABINS)  // 1792
#define INROWS     (TABROWS + BATCH)        // 2304

// ---------------------------------------------------------------------------
// Scratch (static device allocations; no cudaMalloc allowed)
// ---------------------------------------------------------------------------
__device__ float d_xzproj [INROWS * 2 * D_INNER];
__device__ float d_xc     [ROWS * D_INNER];
__device__ float d_delta  [ROWS * D_INNER];
__device__ float d_embed  [ROWS * DIM];
__device__ __align__(16) __nv_bfloat16 d_inA_bf   [INROWS * DIM];
__device__ __align__(16) __nv_bfloat16 d_inproj_bf[2 * D_INNER * DIM];
__device__ __align__(16) __nv_bfloat16 d_outproj_bf[DIM * D_INNER];
__device__ __align__(16) __nv_bfloat16 d_dtproj_bf[D_INNER * DT_RANK];
__device__ __align__(16) __nv_bfloat16 d_xdbl_bf  [ROWS * XD];
__device__ __align__(16) __nv_bfloat16 d_y_bf     [ROWS * D_INNER];

// ---------------------------------------------------------------------------
// Common MMA helpers
// ---------------------------------------------------------------------------
__device__ __forceinline__ void ldsm_x4(unsigned r[4], uint32_t addr) {
    asm volatile("ldmatrix.sync.aligned.m8n8.x4.shared.b16 {%0,%1,%2,%3}, [%4];\n"
                 : "=r"(r[0]), "=r"(r[1]), "=r"(r[2]), "=r"(r[3])
                 : "r"(addr));
}

__device__ __forceinline__ void mma_bf16(float c[4],
                                         const unsigned a[4],
                                         const unsigned b[2]) {
    asm volatile(
        "mma.sync.aligned.m16n8k16.row.col.f32.bf16.bf16.f32 "
        "{%0,%1,%2,%3}, {%4,%5,%6,%7}, {%8,%9}, {%0,%1,%2,%3};\n"
        : "+f"(c[0]), "+f"(c[1]), "+f"(c[2]), "+f"(c[3])
        : "r"(a[0]), "r"(a[1]), "r"(a[2]), "r"(a[3]),
          "r"(b[0]), "r"(b[1]));
}

__device__ __forceinline__ void cp_async16(uint32_t dst, const void* src) {
    asm volatile("cp.async.cg.shared.global [%0], [%1], 16;\n"
                 :: "r"(dst), "l"(src));
}

// ---------------------------------------------------------------------------
// gemm_big: bf16 operands in gmem, fp32 out. C[m,n] = sum_k A[m,k]*B[n,k].
//   Block tile 128x256xBK64, 512 threads = 16 warps (4m x 4n), warp tile 32x64.
//   3-stage cp.async pipeline, one __syncthreads per K-tile. Supports nk==1.
//   Requirements: M%128==0, N%256==0, K%64==0, lda/ldb%8==0.
//   EPI: 0 none | 1 softplus(x + bias[n])
// ---------------------------------------------------------------------------
#define BM2   128
#define BN2   256
#define BK2   64
#define BKP2  72   // pitch (bf16): 144B = 9x16B -> ldmatrix conflict-free
#define ASTG  (BM2 * BKP2 * 2)
#define BSTG  (BN2 * BKP2 * 2)
#define BIG_SMEM (3 * (ASTG + BSTG))   // 165888 B
#define BIG_THREADS 512

template<int EPI>
__global__ __launch_bounds__(BIG_THREADS)
void gemm_big(const __nv_bfloat16* __restrict__ A,
              const __nv_bfloat16* __restrict__ B,
              float* __restrict__ C, int M, int N, int K,
              int lda, int ldb, int ldc,
              const float* __restrict__ bias)
{
    extern __shared__ char smem_raw[];
    const uint32_t sA = (uint32_t)__cvta_generic_to_shared(smem_raw);
    const uint32_t sB = sA + 3 * ASTG;

    const int tid  = threadIdx.x;
    const int warp = tid >> 5;            // 0..15
    const int lane = tid & 31;
    const int wm   = (warp & 3)  * 32;    // 0,32,64,96
    const int wn   = (warp >> 2) * 64;    // 0,64,128,192
    const int gid  = lane >> 2;
    const int tig  = lane & 3;

    const int bm = blockIdx.y * BM2;
    const int bn = blockIdx.x * BN2;

    // R14/15-verified fragment lane mappings
    const int a_row = (lane & 7) + ((lane >> 3) & 1) * 8;
    const uint32_t a_off = (uint32_t)(a_row * BKP2 + (lane >> 4) * 8) * 2;
    const int b_row = (lane & 7) + ((lane >> 4) ? 8 : 0);
    const uint32_t b_off = (uint32_t)(b_row * BKP2 + ((lane >> 3) & 1) * 8) * 2;

    float acc[2][8][4];
    #pragma unroll
    for (int i = 0; i < 2; i++)
        #pragma unroll
        for (int j = 0; j < 8; j++)
            #pragma unroll
            for (int e = 0; e < 4; e++) acc[i][j][e] = 0.f;

    auto stage = [&](int it) {
        const int k0 = it * BK2;
        const int s  = it % 3;
        const uint32_t dA = sA + s * ASTG;
        const uint32_t dB = sB + s * BSTG;
        #pragma unroll
        for (int i = 0; i < 2; i++) {                // A: 1024 16B chunks
            int ci = tid + i * BIG_THREADS;
            int row = ci >> 3, c8 = ci & 7;
            cp_async16(dA + (uint32_t)(row * BKP2 + c8 * 8) * 2,
                       A + (long)(bm + row) * lda + k0 + c8 * 8);
        }
        #pragma unroll
        for (int i = 0; i < 4; i++) {                // B: 2048 16B chunks
            int ci = tid + i * BIG_THREADS;
            int row = ci >> 3, c8 = ci & 7;
            cp_async16(dB + (uint32_t)(row * BKP2 + c8 * 8) * 2,
                       B + (long)(bn + row) * ldb + k0 + c8 * 8);
        }
    };

    const int nk = K / BK2;
    stage(0);
    asm volatile("cp.async.commit_group;");
    if (nk > 1) stage(1);
    asm volatile("cp.async.commit_group;");

    for (int it = 0; it < nk; ++it) {
        asm volatile("cp.async.wait_group 1;");
        __syncthreads();
        if (it + 2 < nk) stage(it + 2);
        asm volatile("cp.async.commit_group;");

        const int s = it % 3;
        const uint32_t aBase = sA + s * ASTG + a_off;
        const uint32_t bBase = sB + s * BSTG + b_off;

        #pragma unroll
        for (int kk = 0; kk < BK2; kk += 16) {
            unsigned a[2][4], b[4][4];
            #pragma unroll
            for (int mt = 0; mt < 2; mt++)
                ldsm_x4(a[mt], aBase + (uint32_t)((wm + mt * 16) * BKP2 + kk) * 2);
            #pragma unroll
            for (int np = 0; np < 4; np++)
                ldsm_x4(b[np], bBase + (uint32_t)((wn + np * 16) * BKP2 + kk) * 2);
            #pragma unroll
            for (int mt = 0; mt < 2; mt++)
                #pragma unroll
                for (int nt = 0; nt < 8; nt++)
                    mma_bf16(acc[mt][nt], a[mt], &b[nt >> 1][(nt & 1) * 2]);
        }
    }

    #pragma unroll
    for (int mt = 0; mt < 2; mt++) {
        int m0 = bm + wm + mt * 16 + gid;
        #pragma unroll
        for (int nt = 0; nt < 8; nt++) {
            int col0 = bn + wn + nt * 8 + tig * 2;
            #pragma unroll
            for (int e = 0; e < 4; e++) {
                int m = m0 + ((e >> 1) ? 8 : 0);
                int n = col0 + (e & 1);
                float v = acc[mt][nt][e];
                if (EPI == 1) {
                    v += bias[n];
                    v = fmaxf(v, 0.f) + log1pf(expf(-fabsf(v)));
                }
                C[(long)m * ldc + n] = v;
            }
        }
    }
}

// ---------------------------------------------------------------------------
// gemm_bf16 (proven): fp32 in gmem, converts at staging. Small GEMMs.
//   OUT: 0 = fp32 C, 1 = bf16 C
// ---------------------------------------------------------------------------
#define BM  128
#define BN  128
#define BK  32
#define BKP 40

__device__ __forceinline__ uint4 cvt8_bf16(const float4& a, const float4& b) {
    __nv_bfloat162 p0 = __float22bfloat162_rn(make_float2(a.x, a.y));
    __nv_bfloat162 p1 = __float22bfloat162_rn(make_float2(a.z, a.w));
    __nv_bfloat162 p2 = __float22bfloat162_rn(make_float2(b.x, b.y));
    __nv_bfloat162 p3 = __float22bfloat162_rn(make_float2(b.z, b.w));
    uint4 u;
    u.x = *reinterpret_cast<unsigned*>(&p0);
    u.y = *reinterpret_cast<unsigned*>(&p1);
    u.z = *reinterpret_cast<unsigned*>(&p2);
    u.w = *reinterpret_cast<unsigned*>(&p3);
    return u;
}

template<int EPI, int OUT>
__global__ __launch_bounds__(256)
void gemm_bf16(const float* __restrict__ Ag, const float* __restrict__ Bg,
               void* __restrict__ Cg, int M, int N, int K,
               int lda, int ldb, int ldc,
               long sAz, long sBz, long sCz,
               const float* __restrict__ bias)
{
    const float* A = Ag + (long)blockIdx.z * sAz;
    const float* B = Bg + (long)blockIdx.z * sBz;
    float*         Cf = (float*)Cg + (long)blockIdx.z * sCz;
    __nv_bfloat16* Cb = (__nv_bfloat16*)Cg + (long)blockIdx.z * sCz;

    __shared__ alignas(16) __nv_bfloat16 As[2][BM][BKP];
    __shared__ alignas(16) __nv_bfloat16 Bs[2][BN][BKP];

    const int tid  = threadIdx.x;
    const int warp = tid >> 5;
    const int lane = tid & 31;
    const int wm   = (warp >> 2) * 64;
    const int wn   = (warp & 3)  * 32;
    const int gid  = lane >> 2;
    const int tig  = lane & 3;

    const int bm = blockIdx.y * BM;
    const int bn = blockIdx.x * BN;

    const int lr = tid >> 2;
    const int lc = (tid & 3) * 8;

    const uint32_t sA = (uint32_t)__cvta_generic_to_shared(&As[0][0][0]);
    const uint32_t sB = (uint32_t)__cvta_generic_to_shared(&Bs[0][0][0]);
    const uint32_t bufBytes = BM * BKP * 2;

    const int a_row = (lane & 7) + ((lane >> 3) & 1) * 8;
    const uint32_t a_off = (uint32_t)(a_row * BKP + (lane >> 4) * 8) * 2;
    const int b_row = (lane & 7) + ((lane >> 4) ? 8 : 0);
    const uint32_t b_off = (uint32_t)(b_row * BKP + ((lane >> 3) & 1) * 8) * 2;

    float acc[4][4][4];
    #pragma unroll
    for (int i = 0; i < 4; i++)
        #pragma unroll
        for (int j = 0; j < 4; j++)
            #pragma unroll
            for (int e = 0; e < 4; e++) acc[i][j][e] = 0.f;

    float4 av[2][2], bv[2][2];
    const float4 z4 = make_float4(0.f, 0.f, 0.f, 0.f);

    auto load_g = [&](int k0) {
        #pragma unroll
        for (int r = 0; r < 2; r++) {
            int row = lr + r * 64;
            #pragma unroll
            for (int q = 0; q < 2; q++)
                av[r][q] = *reinterpret_cast<const float4*>(
                    A + (long)(bm + row) * lda + k0 + lc + q * 4);
            int brow = bn + row;
            #pragma unroll
            for (int q = 0; q < 2; q++)
                bv[r][q] = (brow < N)
                    ? *reinterpret_cast<const float4*>(
                          B + (long)brow * ldb + k0 + lc + q * 4)
                    : z4;
        }
    };

    auto store_s = [&](int buf) {
        #pragma unroll
        for (int r = 0; r < 2; r++) {
            int row = lr + r * 64;
            *reinterpret_cast<uint4*>(&As[buf][row][lc]) =
                cvt8_bf16(av[r][0], av[r][1]);
            *reinterpret_cast<uint4*>(&Bs[buf][row][lc]) =
                cvt8_bf16(bv[r][0], bv[r][1]);
        }
    };

    const int nk = K / BK;
    load_g(0);
    store_s(0);
    __syncthreads();

    for (int it = 0; it < nk; ++it) {
        if (it + 1 < nk) load_g((it + 1) * BK);
        const int buf = it & 1;
        const uint32_t aBase = sA + buf * bufBytes + a_off;
        const uint32_t bBase = sB + buf * bufBytes + b_off;

        #pragma unroll
        for (int kk = 0; kk < BK; kk += 16) {
            unsigned a[4][4], b[2][4];
            #pragma unroll
            for (int mt = 0; mt < 4; mt++)
                ldsm_x4(a[mt], aBase + (uint32_t)((wm + mt * 16) * BKP + kk) * 2);
            #pragma unroll
            for (int np = 0; np < 2; np++)
                ldsm_x4(b[np], bBase + (uint32_t)((wn + np * 16) * BKP + kk) * 2);
            #pragma unroll
            for (int mt = 0; mt < 4; mt++)
                #pragma unroll
                for (int nt = 0; nt < 4; nt++)
                    mma_bf16(acc[mt][nt], a[mt], &b[nt >> 1][(nt & 1) * 2]);
        }

        if (it + 1 < nk) store_s((it + 1) & 1);
        __syncthreads();
    }

    #pragma unroll
    for (int mt = 0; mt < 4; mt++) {
        int m0 = bm + wm + mt * 16 + gid;
        #pragma unroll
        for (int nt = 0; nt < 4; nt++) {
            int col0 = bn + wn + nt * 8 + tig * 2;
            #pragma unroll
            for (int e = 0; e < 4; e++) {
                int m = m0 + ((e >> 1) ? 8 : 0);
                int n = col0 + (e & 1);
                if (n < N) {
                    float v = acc[mt][nt][e];
                    if (EPI == 1) {
                        v += bias[n];
                        v = fmaxf(v, 0.f) + log1pf(expf(-fabsf(v)));
                    }
                    int nout = n;
                    if (EPI == 2) {
                        nout = (n + 255) & 255;
                        v = 1.f / (1.f + __expf(-v));
                    }
                    if (OUT == 1)
                        Cb[(long)m * ldc + nout] = __float2bfloat16(v);
                    else
                        Cf[(long)m * ldc + nout] = v;
                }
            }
        }
    }
}

// ---------------------------------------------------------------------------
// fp32 -> bf16 conversion (n % 4 == 0)
// ---------------------------------------------------------------------------
__global__ void cvt_bf16_kernel(const float* __restrict__ src,
                                __nv_bfloat16* __restrict__ dst, int n)
{
    int i = (blockIdx.x * blockDim.x + threadIdx.x) * 4;
    if (i < n) {
        float4 v = *reinterpret_cast<const float4*>(src + i);
        __nv_bfloat162 p0 = __float22bfloat162_rn(make_float2(v.x, v.y));
        __nv_bfloat162 p1 = __float22bfloat162_rn(make_float2(v.z, v.w));
        uint2 u;
        u.x = *reinterpret_cast<unsigned*>(&p0);
        u.y = *reinterpret_cast<unsigned*>(&p1);
        *reinterpret_cast<uint2*>(dst + i) = u;
    }
}

// ---------------------------------------------------------------------------
// sos mean (float4), written as bf16 into combined in-proj A at row 1792+b
// ---------------------------------------------------------------------------
__global__ void mean_kernel(const float* __restrict__ es,
                            __nv_bfloat16* __restrict__ dst)
{
    int b = blockIdx.x;
    int d4 = threadIdx.x;
    const float4* p = reinterpret_cast<const float4*>(es + (long)b * SEQ * DIM) + d4;
    float4 s = make_float4(0.f, 0.f, 0.f, 0.f);
    #pragma unroll
    for (int t = 0; t < SEQ; t++) {
        float4 v = p[t * (DIM / 4)];
        s.x += v.x; s.y += v.y; s.z += v.z; s.w += v.w;
    }
    const float r = 1.f / SEQ;
    __nv_bfloat162 p0 = __float22bfloat162_rn(make_float2(s.x * r, s.y * r));
    __nv_bfloat162 p1 = __float22bfloat162_rn(make_float2(s.z * r, s.w * r));
    uint2 u;
    u.x = *reinterpret_cast<unsigned*>(&p0);
    u.y = *reinterpret_cast<unsigned*>(&p1);
    *reinterpret_cast<uint2*>(dst + (long)(TABROWS + b) * DIM + d4 * 4) = u;
}

// Row of the (virtual) xz matrix for (batch b, token t) in d_xzproj
__device__ __forceinline__ const float* xz_row(int b, int t,
                                               const int* __restrict__ actions,
                                               const float* __restrict__ xzproj)
{
    int row = (t == 0) ? (TABROWS + b)
                       : ((t - 1) * ABINS + actions[b * (NUM_ACT - 1) + (t - 1)]);
    return xzproj + (long)row * (2 * D_INNER);
}

// ---------------------------------------------------------------------------
// Causal depthwise conv (D_CONV=4) + SiLU, float4. One block per token row.
// ---------------------------------------------------------------------------
__global__ void conv_silu_kernel(const int* __restrict__ actions,
                                 const float* __restrict__ xzproj,
                                 const float* __restrict__ conv_w,
                                 const float* __restrict__ conv_b,
                                 float* __restrict__ xc)
{
    int row = blockIdx.x;
    int b = row >> 3, l = row & 7;
    const float4* p[4];
    #pragma unroll
    for (int k = 0; k < 4; k++) {
        int t = l + k - 3;
        p[k] = (t >= 0)
             ? reinterpret_cast<const float4*>(xz_row(b, t, actions, xzproj))
             : nullptr;
    }
    for (int c4 = threadIdx.x; c4 < D_INNER / 4; c4 += blockDim.x) {
        float4 acc = reinterpret_cast<const float4*>(conv_b)[c4];
        float* a = &acc.x;
        #pragma unroll
        for (int k = 0; k < 4; k++) {
            if (!p[k]) continue;
            float4 v = p[k][c4];
            const float* vv = &v.x;
            #pragma unroll
            for (int j = 0; j < 4; j++)
                a[j] = fmaf(vv[j], conv_w[(c4 * 4 + j) * 4 + k], a[j]);
        }
        float4 o;
        o.x = acc.x / (1.f + __expf(-acc.x));
        o.y = acc.y / (1.f + __expf(-acc.y));
        o.z = acc.z / (1.f + __expf(-acc.z));
        o.w = acc.w / (1.f + __expf(-acc.w));
        reinterpret_cast<float4*>(xc + (long)row * D_INNER)[c4] = o;
    }
}

// ---------------------------------------------------------------------------
// Selective scan + skip + SiLU(z) gate; xdbl in bf16; writes y as bf16
// ---------------------------------------------------------------------------
__global__ void scan_kernel(const float* __restrict__ xc,
                            const float* __restrict__ delta,
                            const __nv_bfloat16* __restrict__ xdbl,
                            const int*   __restrict__ actions,
                            const float* __restrict__ xzproj,
                            const float* __restrict__ A_log,
                            const float* __restrict__ Dp,
                            __nv_bfloat16* __restrict__ y)
{
    int b = blockIdx.x;
    int tid = threadIdx.x;

    __shared__ float Bs[NUM_ACT][D_STATE];
    __shared__ float Cs[NUM_ACT][D_STATE];
    if (tid < NUM_ACT * D_STATE) {
        int l = tid / D_STATE, n = tid % D_STATE;
        const __nv_bfloat16* r = xdbl + (long)(b * NUM_ACT + l) * XD;
        Bs[l][n] = __bfloat162float(r[DT_RANK + n]);
        Cs[l][n] = __bfloat162float(r[DT_RANK + D_STATE + n]);
    }
    __syncthreads();

    const float* zp[NUM_ACT];
    #pragma unroll
    for (int l = 0; l < NUM_ACT; l++)
        zp[l] = xz_row(b, l, actions, xzproj) + D_INNER;

    for (int j = 0; j < D_INNER / 256; j++) {
        int d = tid + j * 256;
        float Arow[D_STATE];
        #pragma unroll
        for (int n = 0; n < D_STATE; n++)
            Arow[n] = -__expf(A_log[d * D_STATE + n]);
        float Dd = Dp[d];
        float h[D_STATE];
        #pragma unroll
        for (int n = 0; n < D_STATE; n++) h[n] = 0.f;

        #pragma unroll
        for (int l = 0; l < NUM_ACT; l++) {
            long row = (long)(b * NUM_ACT + l);
            float dl = delta[row * D_INNER + d];
            float u  = xc[row * D_INNER + d];
            float du = dl * u;
            float yv = 0.f;
            #pragma unroll
            for (int n = 0; n < D_STATE; n++) {
                float dA = __expf(dl * Arow[n]);
                h[n] = fmaf(dA, h[n], du * Bs[l][n]);
                yv   = fmaf(h[n], Cs[l][n], yv);
            }
            yv = fmaf(u, Dd, yv);
            float z = zp[l][d];
            float sz = z / (1.f + __expf(-z));
            y[row * D_INNER + d] = __float2bfloat16(yv * sz);
        }
    }
}

// ---------------------------------------------------------------------------
// Launch
// ---------------------------------------------------------------------------
extern "C" void kernel_launch(void* const* d_in, const int* in_sizes, int n_in,
                              void* d_out, int out_size)
{
    const float* encoded_state = (const float*)d_in[0];
    const int*   actions       = (const int*)  d_in[1];
    const float* tab           = (const float*)d_in[2];   // [8,256,1024]
    /* d_in[3] = gamma (unused by reference) */
    const float* in_proj_w     = (const float*)d_in[4];   // [4096,1024]
    const float* conv_w        = (const float*)d_in[5];
    const float* conv_b        = (const float*)d_in[6];
    const float* x_proj_w      = (const float*)d_in[7];   // [96,2048]
    const float* dt_proj_w     = (const float*)d_in[8];   // [2048,64]
    const float* dt_proj_b     = (const float*)d_in[9];
    const float* A_log         = (const float*)d_in[10];
    const float* D_param       = (const float*)d_in[11];
    const float* out_proj_w    = (const float*)d_in[12];  // [1024,2048]
    float* out = (float*)d_out;                           // [512,8,256]

    float *g_xzproj, *g_xc, *g_delta, *g_embed;
    __nv_bfloat16 *g_inA_bf, *g_inproj_bf, *g_outproj_bf, *g_dtproj_bf,
                  *g_xdbl_bf, *g_y_bf;
    cudaGetSymbolAddress((void**)&g_xzproj,     d_xzproj);
    cudaGetSymbolAddress((void**)&g_xc,         d_xc);
    cudaGetSymbolAddress((void**)&g_delta,      d_delta);
    cudaGetSymbolAddress((void**)&g_embed,      d_embed);
    cudaGetSymbolAddress((void**)&g_inA_bf,     d_inA_bf);
    cudaGetSymbolAddress((void**)&g_inproj_bf,  d_inproj_bf);
    cudaGetSymbolAddress((void**)&g_outproj_bf, d_outproj_bf);
    cudaGetSymbolAddress((void**)&g_dtproj_bf,  d_dtproj_bf);
    cudaGetSymbolAddress((void**)&g_xdbl_bf,    d_xdbl_bf);
    cudaGetSymbolAddress((void**)&g_y_bf,       d_y_bf);

    cudaFuncSetAttribute(gemm_big<0>, cudaFuncAttributeMaxDynamicSharedMemorySize,
                         BIG_SMEM);
    cudaFuncSetAttribute(gemm_big<1>, cudaFuncAttributeMaxDynamicSharedMemorySize,
                         BIG_SMEM);

    // 0) operand conversions to bf16
    const int n_tab = TABROWS * DIM;
    const int n_inp = 2 * D_INNER * DIM;
    const int n_out = DIM * D_INNER;
    const int n_dtp = D_INNER * DT_RANK;
    cvt_bf16_kernel<<<n_tab / 4 / 256, 256>>>(tab, g_inA_bf, n_tab);
    cvt_bf16_kernel<<<n_inp / 4 / 256, 256>>>(in_proj_w, g_inproj_bf, n_inp);
    cvt_bf16_kernel<<<n_out / 4 / 256, 256>>>(out_proj_w, g_outproj_bf, n_out);
    cvt_bf16_kernel<<<n_dtp / 4 / 256, 256>>>(dt_proj_w, g_dtproj_bf, n_dtp);

    // 1) sos = mean(encoded_state) -> bf16 rows [1792, 2304) of inA
    mean_kernel<<<BATCH, 256>>>(encoded_state, g_inA_bf);

    // 2) xzproj = [tab(1792) ; sos(512)] @ in_proj^T  (2304 x 4096, K=1024)
    gemm_big<0><<<dim3(2 * D_INNER / BN2, INROWS / BM2, 1), BIG_THREADS, BIG_SMEM>>>(
        g_inA_bf, g_inproj_bf, g_xzproj, INROWS, 2 * D_INNER, DIM,
        DIM, DIM, 2 * D_INNER, nullptr);

    // 3) xc = silu(causal_conv(xh))
    conv_silu_kernel<<<ROWS, 256>>>(actions, g_xzproj, conv_w, conv_b, g_xc);

    // 4) x_dbl = xc @ x_proj^T  (4096 x 96, K=2048) -> bf16
    gemm_bf16<0, 1><<<dim3(1, ROWS / BM, 1), 256>>>(
        g_xc, x_proj_w, g_xdbl_bf, ROWS, XD, D_INNER,
        D_INNER, D_INNER, XD, 0, 0, 0, nullptr);

    // 5) delta = softplus(dt @ dt_proj^T + b)  (4096 x 2048, K=64)
    gemm_big<1><<<dim3(D_INNER / BN2, ROWS / BM2, 1), BIG_THREADS, BIG_SMEM>>>(
        g_xdbl_bf, g_dtproj_bf, g_delta, ROWS, D_INNER, DT_RANK,
        XD, DT_RANK, D_INNER, dt_proj_b);

    // 6) selective scan -> y (bf16)
    scan_kernel<<<BATCH, 256>>>(g_xc, g_delta, g_xdbl_bf, actions,
                                g_xzproj, A_log, D_param, g_y_bf);

    // 7) embed = y @ out_proj^T  (4096 x 1024, K=2048)
    gemm_big<0><<<dim3(DIM / BN2, ROWS / BM2, 1), BIG_THREADS, BIG_SMEM>>>(
        g_y_bf, g_outproj_bf, g_embed, ROWS, DIM, D_INNER,
        D_INNER, D_INNER, DIM, nullptr);

    // 8) out[b,n,a] = sigmoid(embed . tab[n, (a+1)%256])
    gemm_bf16<2, 0><<<dim3(ABINS / BN, BATCH / BM, NUM_ACT), 256>>>(
        g_embed, tab, out, BATCH, ABINS, DIM,
        NUM_ACT * DIM, DIM, NUM_ACT * ABINS,
        DIM, (long)ABINS * DIM, ABINS,
        nullptr);
}